// round 7
// baseline (speedup 1.0000x reference)
#include <cuda_runtime.h>
#include <cuda_fp16.h>
#include <cuda_bf16.h>
#include <cstdint>

#define N_NODES 50000
#define N_EDGES 800000
#define N_GRAPHS 64
#define HEADS 8
#define NEG_SLOPE 0.2f
#define FULLM 0xffffffffu

// ---------------- scratch (device globals; no allocations allowed) ----------
static __device__ float  g_xp[(size_t)N_NODES * 256];    // projected features (fp32)
static __device__ __half g_xph[(size_t)N_NODES * 256];   // fp16 mirror for gathers
static __device__ float  g_h[(size_t)N_NODES * 256];     // inter-layer node features
static __device__ __half g_hh[(size_t)N_NODES * 256];    // fp16 mirror of layer-2 output
static __device__ float  g_xt[(size_t)N_NODES * 32];     // tf32-rounded x
static __device__ float  g_w1t[256 * 32];
static __device__ float  g_w2t[256 * 256];
static __device__ float  g_als[N_NODES * HEADS];
static __device__ float  g_ald[N_NODES * HEADS];
static __device__ float  g_aself[N_NODES * HEADS];
static __device__ float  g_mx[N_NODES * HEADS];
static __device__ float  g_inv[N_NODES * HEADS];
static __device__ int    g_deg[N_NODES];
static __device__ int    g_rowptr[N_NODES + 1];
static __device__ int    g_cursor[N_NODES];
static __device__ int    g_csrc[N_EDGES];
static __device__ float  g_pool[N_GRAPHS * 2048];
static __device__ float  g_gmean[N_GRAPHS * 256];
static __device__ float  g_wts[HEADS * 256];
static __device__ float  g_wtd[HEADS * 256];

__device__ __forceinline__ float leakyf(float x) { return x > 0.f ? x : NEG_SLOPE * x; }
__device__ __forceinline__ float eluf(float x)   { return x > 0.f ? x : (__expf(x) - 1.f); }

__device__ __forceinline__ uint32_t f2tf32(float x) {
    uint32_t r; asm("cvt.rna.tf32.f32 %0, %1;" : "=r"(r) : "f"(x)); return r;
}
__device__ __forceinline__ float roundtf(float x) { return __uint_as_float(f2tf32(x)); }

__device__ __forceinline__ void mma_tf32(float* c, const uint32_t* a, const uint32_t* b) {
    asm volatile(
        "mma.sync.aligned.m16n8k8.row.col.f32.tf32.tf32.f32 "
        "{%0,%1,%2,%3}, {%4,%5,%6,%7}, {%8,%9}, {%0,%1,%2,%3};\n"
        : "+f"(c[0]), "+f"(c[1]), "+f"(c[2]), "+f"(c[3])
        : "r"(a[0]), "r"(a[1]), "r"(a[2]), "r"(a[3]), "r"(b[0]), "r"(b[1]));
}
__device__ __forceinline__ void cp16(uint32_t sa, const float* g, uint32_t sz) {
    asm volatile("cp.async.cg.shared.global [%0], [%1], 16, %2;\n" :: "r"(sa), "l"(g), "r"(sz));
}

// ---------------- elementwise tf32 rounding ----------------------------------
__global__ void k_round(const float* __restrict__ src, float* __restrict__ dst, int n) {
    int i = blockIdx.x * blockDim.x + threadIdx.x;
    if (i < n) dst[i] = roundtf(src[i]);
}

// ---------------- CSR build --------------------------------------------------
__global__ void k_zero_deg() {
    int i = blockIdx.x * blockDim.x + threadIdx.x;
    if (i < N_NODES) g_deg[i] = 0;
}
__global__ void k_hist(const int* __restrict__ dst) {
    int e = blockIdx.x * blockDim.x + threadIdx.x;
    if (e < N_EDGES) atomicAdd(&g_deg[dst[e]], 1);
}
__global__ void k_scan() {
    __shared__ int wsum[32];
    __shared__ int carry_s;
    int t = threadIdx.x, lane = t & 31, w = t >> 5;
    if (t == 0) carry_s = 0;
    __syncthreads();
    for (int base = 0; base < N_NODES; base += 1024) {
        int i = base + t;
        int v = (i < N_NODES) ? g_deg[i] : 0;
        int x = v;
#pragma unroll
        for (int off = 1; off < 32; off <<= 1) {
            int y = __shfl_up_sync(FULLM, x, off);
            if (lane >= off) x += y;
        }
        if (lane == 31) wsum[w] = x;
        __syncthreads();
        if (w == 0) {
            int s = wsum[lane];
#pragma unroll
            for (int off = 1; off < 32; off <<= 1) {
                int y = __shfl_up_sync(FULLM, s, off);
                if (lane >= off) s += y;
            }
            wsum[lane] = s;
        }
        __syncthreads();
        int c = carry_s;
        int incl = x + ((w > 0) ? wsum[w - 1] : 0);
        if (i < N_NODES) { g_rowptr[i] = c + incl - v; g_cursor[i] = c + incl - v; }
        __syncthreads();
        if (t == 1023) carry_s = c + incl;
        __syncthreads();
    }
    if (t == 0) g_rowptr[N_NODES] = N_EDGES;
}
__global__ void k_scatter(const int* __restrict__ src, const int* __restrict__ dst) {
    int e = blockIdx.x * blockDim.x + threadIdx.x;
    if (e < N_EDGES) {
        int d = dst[e];
        int pos = atomicAdd(&g_cursor[d], 1);
        g_csrc[pos] = src[e];
    }
}

// ---------------- pipelined legacy tf32 GEMM: C[M,256]=A[M,K]*B[256,K]^T -----
#define GSM_A (128 * 32)
#define GSM_B (256 * 32)
#define GSM_BYTES (3 * (GSM_A + GSM_B) * 4)

__global__ __launch_bounds__(256, 1) void k_mma2(
    const float* __restrict__ A, const float* __restrict__ B,
    float* __restrict__ C, __half* __restrict__ Ch,
    int M, int K)
{
    extern __shared__ float smem[];
    float* As = smem;
    float* Bs = smem + 3 * GSM_A;
    uint32_t As_u = (uint32_t)__cvta_generic_to_shared(As);
    uint32_t Bs_u = (uint32_t)__cvta_generic_to_shared(Bs);

    int tid = threadIdx.x;
    int lane = tid & 31, wid = tid >> 5;
    int qm = lane >> 2, qk = lane & 3;
    int wm = (wid >> 2) * 64;
    int wn = (wid & 3) * 64;
    int m0 = blockIdx.x * 128;

    float acc[4][8][4];
#pragma unroll
    for (int mt = 0; mt < 4; mt++)
#pragma unroll
        for (int nt = 0; nt < 8; nt++)
#pragma unroll
            for (int r = 0; r < 4; r++) acc[mt][nt][r] = 0.f;

    auto stage = [&](int s, int k0) {
#pragma unroll
        for (int i = 0; i < 4; i++) {
            int idx = tid + i * 256;
            int r = idx >> 3, cc = idx & 7;
            int gm = m0 + r;
            const float* srcp = A + (size_t)(gm < M ? gm : (M - 1)) * K + k0 + cc * 4;
            uint32_t dstp = As_u + (uint32_t)(s * GSM_A + r * 32 + ((cc ^ (r & 7)) << 2)) * 4u;
            cp16(dstp, srcp, (gm < M) ? 16u : 0u);
        }
#pragma unroll
        for (int i = 0; i < 8; i++) {
            int idx = tid + i * 256;
            int r = idx >> 3, cc = idx & 7;
            const float* srcp = B + (size_t)r * K + k0 + cc * 4;
            uint32_t dstp = Bs_u + (uint32_t)(s * GSM_B + r * 32 + ((cc ^ (r & 7)) << 2)) * 4u;
            cp16(dstp, srcp, 16u);
        }
    };

    int niter = K >> 5;
    stage(0, 0);
    asm volatile("cp.async.commit_group;");
    if (K > 32) stage(1, 32);
    asm volatile("cp.async.commit_group;");

    for (int i = 0; i < niter; i++) {
        asm volatile("cp.async.wait_group 1;");
        __syncthreads();
        int knext = (i + 2) << 5;
        if (knext < K) stage((i + 2) % 3, knext);
        asm volatile("cp.async.commit_group;");

        const float* Ab = As + (i % 3) * GSM_A;
        const float* Bb = Bs + (i % 3) * GSM_B;
#pragma unroll
        for (int ks = 0; ks < 4; ks++) {
            int lo  = (((2 * ks)     ^ qm) << 2) + qk;
            int hi2 = (((2 * ks + 1) ^ qm) << 2) + qk;
            uint32_t af[4][4], bf[8][2];
#pragma unroll
            for (int mt = 0; mt < 4; mt++) {
                int rm = wm + mt * 16 + qm;
                af[mt][0] = __float_as_uint(Ab[rm * 32 + lo]);
                af[mt][1] = __float_as_uint(Ab[(rm + 8) * 32 + lo]);
                af[mt][2] = __float_as_uint(Ab[rm * 32 + hi2]);
                af[mt][3] = __float_as_uint(Ab[(rm + 8) * 32 + hi2]);
            }
#pragma unroll
            for (int nt = 0; nt < 8; nt++) {
                int rn = wn + nt * 8 + qm;
                bf[nt][0] = __float_as_uint(Bb[rn * 32 + lo]);
                bf[nt][1] = __float_as_uint(Bb[rn * 32 + hi2]);
            }
#pragma unroll
            for (int mt = 0; mt < 4; mt++)
#pragma unroll
                for (int nt = 0; nt < 8; nt++)
                    mma_tf32(acc[mt][nt], af[mt], bf[nt]);
        }
        __syncthreads();
    }

#pragma unroll
    for (int mt = 0; mt < 4; mt++) {
#pragma unroll
        for (int nt = 0; nt < 8; nt++) {
            int gm = m0 + wm + mt * 16 + qm;
            int gn = wn + nt * 8 + 2 * qk;
            if (gm < M) {
                C[(size_t)gm * 256 + gn]     = acc[mt][nt][0];
                C[(size_t)gm * 256 + gn + 1] = acc[mt][nt][1];
                __half2 hv = __floats2half2_rn(acc[mt][nt][0], acc[mt][nt][1]);
                *(__half2*)(Ch + (size_t)gm * 256 + gn) = hv;
            }
            if (gm + 8 < M) {
                C[(size_t)(gm + 8) * 256 + gn]     = acc[mt][nt][2];
                C[(size_t)(gm + 8) * 256 + gn + 1] = acc[mt][nt][3];
                __half2 hv = __floats2half2_rn(acc[mt][nt][2], acc[mt][nt][3]);
                *(__half2*)(Ch + (size_t)(gm + 8) * 256 + gn) = hv;
            }
        }
    }
}

// ---------------- attention logits from xp (layers 1,2) ----------------------
__global__ void k_al(const float* __restrict__ xp, const float* __restrict__ as_,
                     const float* __restrict__ ad_)
{
    int n = blockIdx.x;
    int w = threadIdx.x >> 5, lane = threadIdx.x & 31;
    float v = xp[(size_t)n * 256 + w * 32 + lane];
    float s1 = v * as_[w * 32 + lane];
    float s2 = v * ad_[w * 32 + lane];
#pragma unroll
    for (int o = 16; o; o >>= 1) {
        s1 += __shfl_down_sync(FULLM, s1, o);
        s2 += __shfl_down_sync(FULLM, s2, o);
    }
    if (lane == 0) {
        g_als[n * HEADS + w] = s1;
        g_ald[n * HEADS + w] = s2;
    }
}

// ---------------- layer-3 folded attention vectors ---------------------------
__global__ void k_fold3(const float* __restrict__ W3, const float* __restrict__ as3,
                        const float* __restrict__ ad3)
{
    int idx = blockIdx.x * blockDim.x + threadIdx.x;
    if (idx >= HEADS * 256) return;
    int h = idx >> 8, k = idx & 255;
    float s1 = 0.f, s2 = 0.f;
    for (int d = 0; d < 256; d++) {
        float w = W3[(size_t)(h * 256 + d) * 256 + k];
        s1 += as3[h * 256 + d] * w;
        s2 += ad3[h * 256 + d] * w;
    }
    g_wts[idx] = s1;
    g_wtd[idx] = s2;
}

__global__ void k_al3(const float* __restrict__ h) {
    int n = blockIdx.x;
    int w = threadIdx.x >> 5, lane = threadIdx.x & 31;
    const float* row = h + (size_t)n * 256;
    float s1 = 0.f, s2 = 0.f;
    for (int i = lane; i < 256; i += 32) {
        float v = row[i];
        s1 += v * g_wts[w * 256 + i];
        s2 += v * g_wtd[w * 256 + i];
    }
#pragma unroll
    for (int o = 16; o; o >>= 1) {
        s1 += __shfl_down_sync(FULLM, s1, o);
        s2 += __shfl_down_sync(FULLM, s2, o);
    }
    if (lane == 0) {
        g_als[n * HEADS + w] = s1;
        g_ald[n * HEADS + w] = s2;
    }
}

// ---------------- fused softmax + aggregation (layers 1,2) -------------------
// warp per node; fp16 neighbor-row gathers; 4-edge chunks in pass 2
__global__ void k_gat32(const float* __restrict__ xp, const __half* __restrict__ xph,
                        const float* __restrict__ bias,
                        float* __restrict__ out, __half* __restrict__ out_h)
{
    int n = blockIdx.x * (blockDim.x >> 5) + (threadIdx.x >> 5);
    if (n >= N_NODES) return;
    int lane = threadIdx.x & 31;
    int j = lane >> 3, hd = lane & 7;
    int lo = g_rowptr[n], hi = g_rowptr[n + 1];
    float adh = g_ald[n * HEADS + hd];

    // pass 1: online (m, den) per head, 4-way edge split
    float m = -INFINITY, den = 0.f;
    for (int p = lo + j; p < hi; p += 4) {
        int s = g_csrc[p];
        float e = leakyf(g_als[s * HEADS + hd] + adh);
        if (e > m) { den = den * __expf(m - e) + 1.f; m = e; }
        else       { den += __expf(e - m); }
    }
#pragma unroll
    for (int off = 8; off <= 16; off <<= 1) {
        float mo = __shfl_xor_sync(FULLM, m, off);
        float dn = __shfl_xor_sync(FULLM, den, off);
        float mn = fmaxf(m, mo);
        float t1 = (m  == -INFINITY) ? 0.f : den * __expf(m - mn);
        float t2 = (mo == -INFINITY) ? 0.f : dn  * __expf(mo - mn);
        den = t1 + t2; m = mn;
    }
    float eself = leakyf(g_als[n * HEADS + hd] + adh);
    float mn = fmaxf(m, eself);
    den = ((m == -INFINITY) ? 0.f : den * __expf(m - mn)) + __expf(eself - mn);
    m = mn;
    float inv = 1.f / den;

    // pass 2: 4 edges per iteration; lane = edge j, head hd
    float acc[HEADS];
    {
        float av = __expf(eself - m) * inv;   // identical within hd group
        const float* row = xp + (size_t)n * 256;
#pragma unroll
        for (int k = 0; k < HEADS; k++)
            acc[k] = __shfl_sync(FULLM, av, k) * row[k * 32 + lane];
    }
    for (int p = lo; p < hi; p += 4) {
        int pp = p + j;
        int s = g_csrc[(pp < hi) ? pp : (hi - 1)];
        float e = leakyf(g_als[s * HEADS + hd] + adh);
        float av = (pp < hi) ? __expf(e - m) * inv : 0.f;
#pragma unroll
        for (int ee = 0; ee < 4; ee++) {
            if (p + ee >= hi) break;                       // warp-uniform
            int se = __shfl_sync(FULLM, s, ee * 8);
            const __half* row = xph + (size_t)se * 256;
#pragma unroll
            for (int k = 0; k < HEADS; k++)
                acc[k] += __shfl_sync(FULLM, av, ee * 8 + k) *
                          __half2float(row[k * 32 + lane]);
        }
    }
#pragma unroll
    for (int k = 0; k < HEADS; k++) {
        float v = eluf(acc[k] + bias[k * 32 + lane]);
        out[(size_t)n * 256 + k * 32 + lane] = roundtf(v);
        if (out_h) out_h[(size_t)n * 256 + k * 32 + lane] = __float2half_rn(v);
    }
}

// ---------------- layer-3 softmax (stats only; no alpha buffer) --------------
__global__ void k_softmax() {
    int n = blockIdx.x * (blockDim.x >> 5) + (threadIdx.x >> 5);
    if (n >= N_NODES) return;
    int lane = threadIdx.x & 31;
    int j = lane >> 3, hd = lane & 7;
    int lo = g_rowptr[n], hi = g_rowptr[n + 1];
    float adh = g_ald[n * HEADS + hd];
    float m = -INFINITY, den = 0.f;
    for (int p = lo + j; p < hi; p += 4) {
        int s = g_csrc[p];
        float e = leakyf(g_als[s * HEADS + hd] + adh);
        if (e > m) { den = den * __expf(m - e) + 1.f; m = e; }
        else       { den += __expf(e - m); }
    }
#pragma unroll
    for (int off = 8; off <= 16; off <<= 1) {
        float mo = __shfl_xor_sync(FULLM, m, off);
        float dn = __shfl_xor_sync(FULLM, den, off);
        float mn = fmaxf(m, mo);
        float t1 = (m  == -INFINITY) ? 0.f : den * __expf(m - mn);
        float t2 = (mo == -INFINITY) ? 0.f : dn  * __expf(mo - mn);
        den = t1 + t2; m = mn;
    }
    float eself = leakyf(g_als[n * HEADS + hd] + adh);
    float mn = fmaxf(m, eself);
    den = ((m == -INFINITY) ? 0.f : den * __expf(m - mn)) + __expf(eself - mn);
    m = mn;
    float inv = 1.f / den;
    if (lane < 8) {
        g_aself[n * HEADS + hd] = __expf(eself - m) * inv;
        g_mx[n * HEADS + hd] = m;
        g_inv[n * HEADS + hd] = inv;
    }
}

// ---------------- zero per-graph pool ----------------------------------------
__global__ void k_zero_pool() {
    int i = blockIdx.x * blockDim.x + threadIdx.x;
    if (i < N_GRAPHS * 2048) g_pool[i] = 0.f;
}

// ---------------- layer-3 aggregation fused with graph pooling ---------------
__global__ void k_aggH_pool(const float* __restrict__ h, const __half* __restrict__ hh,
                            const int* __restrict__ batch)
{
    int n0 = blockIdx.x * 32;
    int t = threadIdx.x;   // 256
    __shared__ float a_sm[32][HEADS];
    __shared__ float m_s[HEADS], i_s[HEADS], ad_s[HEADS];
    int nend = min(n0 + 32, N_NODES);
    if (n0 >= N_NODES) return;
    float pacc[HEADS];
#pragma unroll
    for (int k = 0; k < HEADS; k++) pacc[k] = 0.f;
    int prevb = batch[n0];

    for (int n = n0; n < nend; n++) {
        int bn = batch[n];
        if (bn != prevb) {
#pragma unroll
            for (int k = 0; k < HEADS; k++) {
                atomicAdd(&g_pool[prevb * 2048 + k * 256 + t], pacc[k]);
                pacc[k] = 0.f;
            }
            prevb = bn;
        }
        __syncthreads();
        if (t < 8) {
            m_s[t] = g_mx[n * HEADS + t];
            i_s[t] = g_inv[n * HEADS + t];
            ad_s[t] = g_ald[n * HEADS + t];
        }
        __syncthreads();
        int lo = g_rowptr[n], hi = g_rowptr[n + 1];
        float hv = h[(size_t)n * 256 + t];
        float acc[HEADS];
#pragma unroll
        for (int k = 0; k < HEADS; k++)
            acc[k] = g_aself[n * HEADS + k] * hv;
        for (int p0 = lo; p0 < hi; p0 += 32) {
            int cnt = min(32, hi - p0);
            __syncthreads();
            if (t < cnt * HEADS) {
                int jj = t >> 3, hd2 = t & 7;
                int s = g_csrc[p0 + jj];
                float e = leakyf(g_als[s * HEADS + hd2] + ad_s[hd2]);
                a_sm[jj][hd2] = __expf(e - m_s[hd2]) * i_s[hd2];
            }
            __syncthreads();
            for (int jj = 0; jj < cnt; jj++) {
                int s = g_csrc[p0 + jj];
                float hv2 = __half2float(hh[(size_t)s * 256 + t]);
#pragma unroll
                for (int k = 0; k < HEADS; k++)
                    acc[k] += a_sm[jj][k] * hv2;
            }
        }
#pragma unroll
        for (int k = 0; k < HEADS; k++) pacc[k] += acc[k];
    }
#pragma unroll
    for (int k = 0; k < HEADS; k++)
        atomicAdd(&g_pool[prevb * 2048 + k * 256 + t], pacc[k]);
}

// ---------------- layer-3 projection of pooled means -------------------------
__device__ __forceinline__ int lower_bound_batch(const int* b, int val) {
    int lo = 0, hi = N_NODES;
    while (lo < hi) {
        int mid = (lo + hi) >> 1;
        if (b[mid] < val) lo = mid + 1; else hi = mid;
    }
    return lo;
}
__global__ void k_out3(const float* __restrict__ W3, const float* __restrict__ b3,
                       const int* __restrict__ batch)
{
    int g = blockIdx.x;
    int d = threadIdx.x;  // 256
    int lo = lower_bound_batch(batch, g);
    int hi = lower_bound_batch(batch, g + 1);
    float cnt = (float)max(hi - lo, 1);
    float s = 0.f;
#pragma unroll
    for (int h = 0; h < HEADS; h++) {
        const float* wrow = W3 + (size_t)(h * 256 + d) * 256;
        const float* prow = g_pool + g * 2048 + h * 256;
        for (int k = 0; k < 256; k++) s += prow[k] * wrow[k];
    }
    g_gmean[g * 256 + d] = 0.125f * s / cnt + b3[d];
}

// ---------------- classifier MLP ---------------------------------------------
__global__ void k_classifier(const float* __restrict__ Wc1, const float* __restrict__ bc1,
                             const float* __restrict__ Wc2, const float* __restrict__ bc2,
                             float* __restrict__ out)
{
    int g = blockIdx.x;
    int t = threadIdx.x;  // 128
    __shared__ float z[128];
    const float* gr = g_gmean + g * 256;
    float s = bc1[t];
    for (int k = 0; k < 256; k++) s += gr[k] * Wc1[t * 256 + k];
    z[t] = eluf(s);
    __syncthreads();
    if (t < 2) {
        float o = bc2[t];
        for (int jj = 0; jj < 128; jj++) o += z[jj] * Wc2[t * 128 + jj];
        out[g * 2 + t] = o;
    }
}

// ---------------- launch -----------------------------------------------------
extern "C" void kernel_launch(void* const* d_in, const int* in_sizes, int n_in,
                              void* d_out, int out_size)
{
    const float* x      = (const float*)d_in[0];
    const int*   eidx   = (const int*)d_in[1];
    const int*   batch  = (const int*)d_in[2];
    const float* W1  = (const float*)d_in[3];
    const float* as1 = (const float*)d_in[4];
    const float* ad1 = (const float*)d_in[5];
    const float* b1  = (const float*)d_in[6];
    const float* W2  = (const float*)d_in[7];
    const float* as2 = (const float*)d_in[8];
    const float* ad2 = (const float*)d_in[9];
    const float* b2  = (const float*)d_in[10];
    const float* W3  = (const float*)d_in[11];
    const float* as3 = (const float*)d_in[12];
    const float* ad3 = (const float*)d_in[13];
    const float* b3  = (const float*)d_in[14];
    const float* Wc1 = (const float*)d_in[15];
    const float* bc1 = (const float*)d_in[16];
    const float* Wc2 = (const float*)d_in[17];
    const float* bc2 = (const float*)d_in[18];
    float* out = (float*)d_out;

    const int* src = eidx;
    const int* dst = eidx + N_EDGES;

    float*  xp  = nullptr; cudaGetSymbolAddress((void**)&xp,  g_xp);
    __half* xph = nullptr; cudaGetSymbolAddress((void**)&xph, g_xph);
    float*  h   = nullptr; cudaGetSymbolAddress((void**)&h,   g_h);
    __half* hh  = nullptr; cudaGetSymbolAddress((void**)&hh,  g_hh);
    float*  xt  = nullptr; cudaGetSymbolAddress((void**)&xt,  g_xt);
    float*  w1t = nullptr; cudaGetSymbolAddress((void**)&w1t, g_w1t);
    float*  w2t = nullptr; cudaGetSymbolAddress((void**)&w2t, g_w2t);

    cudaFuncSetAttribute(k_mma2, cudaFuncAttributeMaxDynamicSharedMemorySize, GSM_BYTES);

    int gm = (N_NODES + 127) / 128;
    int nwb = (N_NODES + 7) / 8;

    // launch #4 is profiled by ncu -> put the L1 tf32 GEMM there
    k_round<<<(N_NODES * 32 + 255) / 256, 256>>>(x, xt, N_NODES * 32);     // 1
    k_round<<<(256 * 32 + 255) / 256, 256>>>(W1, w1t, 256 * 32);           // 2
    k_zero_deg<<<(N_NODES + 255) / 256, 256>>>();                          // 3
    k_mma2<<<gm, 256, GSM_BYTES>>>(xt, w1t, xp, xph, N_NODES, 32);         // 4 (profiled)
    k_hist<<<(N_EDGES + 255) / 256, 256>>>(dst);                           // 5
    k_scan<<<1, 1024>>>();                                                 // 6
    k_scatter<<<(N_EDGES + 255) / 256, 256>>>(src, dst);                   // 7
    k_round<<<(256 * 256 + 255) / 256, 256>>>(W2, w2t, 256 * 256);         // 8
    k_fold3<<<(2048 + 127) / 128, 128>>>(W3, as3, ad3);                    // 9
    k_zero_pool<<<(N_GRAPHS * 2048 + 255) / 256, 256>>>();                 // 10

    // ---- layer 1
    k_al<<<N_NODES, 256>>>(xp, as1, ad1);
    k_gat32<<<nwb, 256>>>(xp, xph, b1, h, nullptr);

    // ---- layer 2
    k_mma2<<<gm, 256, GSM_BYTES>>>(h, w2t, xp, xph, N_NODES, 256);
    k_al<<<N_NODES, 256>>>(xp, as2, ad2);
    k_gat32<<<nwb, 256>>>(xp, xph, b2, h, hh);

    // ---- layer 3: folded al, stats-only softmax, fused agg+pool, tiny proj
    k_al3<<<N_NODES, 256>>>(h);
    k_softmax<<<nwb, 256>>>();
    k_aggH_pool<<<(N_NODES + 31) / 32, 256>>>(h, hh, batch);
    k_out3<<<N_GRAPHS, 256>>>(W3, b3, batch);

    // ---- classifier
    k_classifier<<<N_GRAPHS, 128>>>(Wc1, bc1, Wc2, bc2, out);
}

// round 8
// speedup vs baseline: 1.1388x; 1.1388x over previous
#include <cuda_runtime.h>
#include <cuda_fp16.h>
#include <cuda_bf16.h>
#include <cstdint>

#define N_NODES 50000
#define N_EDGES 800000
#define N_GRAPHS 64
#define HEADS 8
#define NEG_SLOPE 0.2f
#define FULLM 0xffffffffu

// ---------------- scratch (device globals; no allocations allowed) ----------
static __device__ float  g_xp[(size_t)N_NODES * 256];    // projected features (fp32)
static __device__ __half g_xph[(size_t)N_NODES * 256];   // fp16 mirror for gathers
static __device__ float  g_h[(size_t)N_NODES * 256];     // inter-layer node features
static __device__ __half g_hh[(size_t)N_NODES * 256];    // fp16 mirror of layer-2 output
static __device__ float  g_xt[(size_t)N_NODES * 32];     // tf32-rounded x
static __device__ float  g_w1t[256 * 32];
static __device__ float  g_w2t[256 * 256];
static __device__ float  g_als[N_NODES * HEADS];
static __device__ float  g_ald[N_NODES * HEADS];
static __device__ int    g_deg[N_NODES];
static __device__ int    g_rowptr[N_NODES + 1];
static __device__ int    g_cursor[N_NODES];
static __device__ int    g_csrc[N_EDGES];
static __device__ float  g_pool[N_GRAPHS * 2048];
static __device__ float  g_gmean[N_GRAPHS * 256];
static __device__ float  g_wts[HEADS * 256];
static __device__ float  g_wtd[HEADS * 256];

__device__ __forceinline__ float leakyf(float x) { return x > 0.f ? x : NEG_SLOPE * x; }
__device__ __forceinline__ float eluf(float x)   { return x > 0.f ? x : (__expf(x) - 1.f); }

__device__ __forceinline__ uint32_t f2tf32(float x) {
    uint32_t r; asm("cvt.rna.tf32.f32 %0, %1;" : "=r"(r) : "f"(x)); return r;
}
__device__ __forceinline__ float roundtf(float x) { return __uint_as_float(f2tf32(x)); }

__device__ __forceinline__ void mma_tf32(float* c, const uint32_t* a, const uint32_t* b) {
    asm volatile(
        "mma.sync.aligned.m16n8k8.row.col.f32.tf32.tf32.f32 "
        "{%0,%1,%2,%3}, {%4,%5,%6,%7}, {%8,%9}, {%0,%1,%2,%3};\n"
        : "+f"(c[0]), "+f"(c[1]), "+f"(c[2]), "+f"(c[3])
        : "r"(a[0]), "r"(a[1]), "r"(a[2]), "r"(a[3]), "r"(b[0]), "r"(b[1]));
}
__device__ __forceinline__ void cp16(uint32_t sa, const float* g, uint32_t sz) {
    asm volatile("cp.async.cg.shared.global [%0], [%1], 16, %2;\n" :: "r"(sa), "l"(g), "r"(sz));
}

// ---------------- elementwise tf32 rounding ----------------------------------
__global__ void k_round(const float* __restrict__ src, float* __restrict__ dst, int n) {
    int i = blockIdx.x * blockDim.x + threadIdx.x;
    if (i < n) dst[i] = roundtf(src[i]);
}

// ---------------- CSR build --------------------------------------------------
__global__ void k_zero_deg() {
    int i = blockIdx.x * blockDim.x + threadIdx.x;
    if (i < N_NODES) g_deg[i] = 0;
}
__global__ void k_hist(const int* __restrict__ dst) {
    int e = blockIdx.x * blockDim.x + threadIdx.x;
    if (e < N_EDGES) atomicAdd(&g_deg[dst[e]], 1);
}
__global__ void k_scan() {
    __shared__ int wsum[32];
    __shared__ int carry_s;
    int t = threadIdx.x, lane = t & 31, w = t >> 5;
    if (t == 0) carry_s = 0;
    __syncthreads();
    for (int base = 0; base < N_NODES; base += 1024) {
        int i = base + t;
        int v = (i < N_NODES) ? g_deg[i] : 0;
        int x = v;
#pragma unroll
        for (int off = 1; off < 32; off <<= 1) {
            int y = __shfl_up_sync(FULLM, x, off);
            if (lane >= off) x += y;
        }
        if (lane == 31) wsum[w] = x;
        __syncthreads();
        if (w == 0) {
            int s = wsum[lane];
#pragma unroll
            for (int off = 1; off < 32; off <<= 1) {
                int y = __shfl_up_sync(FULLM, s, off);
                if (lane >= off) s += y;
            }
            wsum[lane] = s;
        }
        __syncthreads();
        int c = carry_s;
        int incl = x + ((w > 0) ? wsum[w - 1] : 0);
        if (i < N_NODES) { g_rowptr[i] = c + incl - v; g_cursor[i] = c + incl - v; }
        __syncthreads();
        if (t == 1023) carry_s = c + incl;
        __syncthreads();
    }
    if (t == 0) g_rowptr[N_NODES] = N_EDGES;
}
__global__ void k_scatter(const int* __restrict__ src, const int* __restrict__ dst) {
    int e = blockIdx.x * blockDim.x + threadIdx.x;
    if (e < N_EDGES) {
        int d = dst[e];
        int pos = atomicAdd(&g_cursor[d], 1);
        g_csrc[pos] = src[e];
    }
}

// ---------------- pipelined legacy tf32 GEMM: C[M,256]=A[M,K]*B[256,K]^T -----
#define GSM_A (128 * 32)
#define GSM_B (256 * 32)
#define GSM_BYTES (3 * (GSM_A + GSM_B) * 4)

__global__ __launch_bounds__(256, 1) void k_mma2(
    const float* __restrict__ A, const float* __restrict__ B,
    float* __restrict__ C, __half* __restrict__ Ch,
    int M, int K)
{
    extern __shared__ float smem[];
    float* As = smem;
    float* Bs = smem + 3 * GSM_A;
    uint32_t As_u = (uint32_t)__cvta_generic_to_shared(As);
    uint32_t Bs_u = (uint32_t)__cvta_generic_to_shared(Bs);

    int tid = threadIdx.x;
    int lane = tid & 31, wid = tid >> 5;
    int qm = lane >> 2, qk = lane & 3;
    int wm = (wid >> 2) * 64;
    int wn = (wid & 3) * 64;
    int m0 = blockIdx.x * 128;

    float acc[4][8][4];
#pragma unroll
    for (int mt = 0; mt < 4; mt++)
#pragma unroll
        for (int nt = 0; nt < 8; nt++)
#pragma unroll
            for (int r = 0; r < 4; r++) acc[mt][nt][r] = 0.f;

    auto stage = [&](int s, int k0) {
#pragma unroll
        for (int i = 0; i < 4; i++) {
            int idx = tid + i * 256;
            int r = idx >> 3, cc = idx & 7;
            int gm = m0 + r;
            const float* srcp = A + (size_t)(gm < M ? gm : (M - 1)) * K + k0 + cc * 4;
            uint32_t dstp = As_u + (uint32_t)(s * GSM_A + r * 32 + ((cc ^ (r & 7)) << 2)) * 4u;
            cp16(dstp, srcp, (gm < M) ? 16u : 0u);
        }
#pragma unroll
        for (int i = 0; i < 8; i++) {
            int idx = tid + i * 256;
            int r = idx >> 3, cc = idx & 7;
            const float* srcp = B + (size_t)r * K + k0 + cc * 4;
            uint32_t dstp = Bs_u + (uint32_t)(s * GSM_B + r * 32 + ((cc ^ (r & 7)) << 2)) * 4u;
            cp16(dstp, srcp, 16u);
        }
    };

    int niter = K >> 5;
    stage(0, 0);
    asm volatile("cp.async.commit_group;");
    if (K > 32) stage(1, 32);
    asm volatile("cp.async.commit_group;");

    for (int i = 0; i < niter; i++) {
        asm volatile("cp.async.wait_group 1;");
        __syncthreads();
        int knext = (i + 2) << 5;
        if (knext < K) stage((i + 2) % 3, knext);
        asm volatile("cp.async.commit_group;");

        const float* Ab = As + (i % 3) * GSM_A;
        const float* Bb = Bs + (i % 3) * GSM_B;
#pragma unroll
        for (int ks = 0; ks < 4; ks++) {
            int lo  = (((2 * ks)     ^ qm) << 2) + qk;
            int hi2 = (((2 * ks + 1) ^ qm) << 2) + qk;
            uint32_t af[4][4], bf[8][2];
#pragma unroll
            for (int mt = 0; mt < 4; mt++) {
                int rm = wm + mt * 16 + qm;
                af[mt][0] = __float_as_uint(Ab[rm * 32 + lo]);
                af[mt][1] = __float_as_uint(Ab[(rm + 8) * 32 + lo]);
                af[mt][2] = __float_as_uint(Ab[rm * 32 + hi2]);
                af[mt][3] = __float_as_uint(Ab[(rm + 8) * 32 + hi2]);
            }
#pragma unroll
            for (int nt = 0; nt < 8; nt++) {
                int rn = wn + nt * 8 + qm;
                bf[nt][0] = __float_as_uint(Bb[rn * 32 + lo]);
                bf[nt][1] = __float_as_uint(Bb[rn * 32 + hi2]);
            }
#pragma unroll
            for (int mt = 0; mt < 4; mt++)
#pragma unroll
                for (int nt = 0; nt < 8; nt++)
                    mma_tf32(acc[mt][nt], af[mt], bf[nt]);
        }
        __syncthreads();
    }

#pragma unroll
    for (int mt = 0; mt < 4; mt++) {
#pragma unroll
        for (int nt = 0; nt < 8; nt++) {
            int gm = m0 + wm + mt * 16 + qm;
            int gn = wn + nt * 8 + 2 * qk;
            if (gm < M) {
                C[(size_t)gm * 256 + gn]     = acc[mt][nt][0];
                C[(size_t)gm * 256 + gn + 1] = acc[mt][nt][1];
                __half2 hv = __floats2half2_rn(acc[mt][nt][0], acc[mt][nt][1]);
                *(__half2*)(Ch + (size_t)gm * 256 + gn) = hv;
            }
            if (gm + 8 < M) {
                C[(size_t)(gm + 8) * 256 + gn]     = acc[mt][nt][2];
                C[(size_t)(gm + 8) * 256 + gn + 1] = acc[mt][nt][3];
                __half2 hv = __floats2half2_rn(acc[mt][nt][2], acc[mt][nt][3]);
                *(__half2*)(Ch + (size_t)(gm + 8) * 256 + gn) = hv;
            }
        }
    }
}

// ---------------- attention logits from xp (layers 1,2) ----------------------
__global__ void k_al(const float* __restrict__ xp, const float* __restrict__ as_,
                     const float* __restrict__ ad_)
{
    int n = blockIdx.x;
    int w = threadIdx.x >> 5, lane = threadIdx.x & 31;
    float v = xp[(size_t)n * 256 + w * 32 + lane];
    float s1 = v * as_[w * 32 + lane];
    float s2 = v * ad_[w * 32 + lane];
#pragma unroll
    for (int o = 16; o; o >>= 1) {
        s1 += __shfl_down_sync(FULLM, s1, o);
        s2 += __shfl_down_sync(FULLM, s2, o);
    }
    if (lane == 0) {
        g_als[n * HEADS + w] = s1;
        g_ald[n * HEADS + w] = s2;
    }
}

// ---------------- layer-3 folded attention vectors ---------------------------
__global__ void k_fold3(const float* __restrict__ W3, const float* __restrict__ as3,
                        const float* __restrict__ ad3)
{
    int idx = blockIdx.x * blockDim.x + threadIdx.x;
    if (idx >= HEADS * 256) return;
    int h = idx >> 8, k = idx & 255;
    float s1 = 0.f, s2 = 0.f;
    for (int d = 0; d < 256; d++) {
        float w = W3[(size_t)(h * 256 + d) * 256 + k];
        s1 += as3[h * 256 + d] * w;
        s2 += ad3[h * 256 + d] * w;
    }
    g_wts[idx] = s1;
    g_wtd[idx] = s2;
}

__global__ void k_al3(const float* __restrict__ h) {
    int n = blockIdx.x;
    int w = threadIdx.x >> 5, lane = threadIdx.x & 31;
    const float* row = h + (size_t)n * 256;
    float s1 = 0.f, s2 = 0.f;
    for (int i = lane; i < 256; i += 32) {
        float v = row[i];
        s1 += v * g_wts[w * 256 + i];
        s2 += v * g_wtd[w * 256 + i];
    }
#pragma unroll
    for (int o = 16; o; o >>= 1) {
        s1 += __shfl_down_sync(FULLM, s1, o);
        s2 += __shfl_down_sync(FULLM, s2, o);
    }
    if (lane == 0) {
        g_als[n * HEADS + w] = s1;
        g_ald[n * HEADS + w] = s2;
    }
}

// ---------------- single-pass GAT layer (softmax+agg fused, no max pass) -----
// warp per node. Lane L evaluates head (L&7) for every edge; den[h] lives in
// lane h (lanes 0..7). Features: lane L owns dims [L*4,L*4+4) and [128+L*4,..).
__global__ void k_gat32(const float* __restrict__ xp, const __half* __restrict__ xph,
                        const float* __restrict__ bias,
                        float* __restrict__ out, __half* __restrict__ out_h)
{
    int n = blockIdx.x * (blockDim.x >> 5) + (threadIdx.x >> 5);
    if (n >= N_NODES) return;
    int lane = threadIdx.x & 31;
    int hd = lane & 7;       // head evaluated by this lane
    int h0 = lane >> 3;      // head owning chunk-0 features (0..3); chunk-1: 4+h0
    int lo = g_rowptr[n], hi = g_rowptr[n + 1];
    float adh = g_ald[n * HEADS + hd];

    float acc[8];
    float den;
    {   // self term (fp32 row)
        float av = __expf(leakyf(g_als[n * HEADS + hd] + adh));
        den = av;
        float av0 = __shfl_sync(FULLM, av, h0);
        float av1 = __shfl_sync(FULLM, av, 4 + h0);
        float4 v0 = *(const float4*)(xp + (size_t)n * 256 + lane * 4);
        float4 v1 = *(const float4*)(xp + (size_t)n * 256 + 128 + lane * 4);
        acc[0] = av0 * v0.x; acc[1] = av0 * v0.y; acc[2] = av0 * v0.z; acc[3] = av0 * v0.w;
        acc[4] = av1 * v1.x; acc[5] = av1 * v1.y; acc[6] = av1 * v1.z; acc[7] = av1 * v1.w;
    }
    for (int p = lo; p < hi; p++) {
        int s = g_csrc[p];
        float av = __expf(leakyf(g_als[s * HEADS + hd] + adh));
        den += av;
        float av0 = __shfl_sync(FULLM, av, h0);
        float av1 = __shfl_sync(FULLM, av, 4 + h0);
        uint2 u0 = *(const uint2*)(xph + (size_t)s * 256 + lane * 4);
        uint2 u1 = *(const uint2*)(xph + (size_t)s * 256 + 128 + lane * 4);
        float2 fa = __half22float2(*(__half2*)&u0.x);
        float2 fb = __half22float2(*(__half2*)&u0.y);
        float2 fc = __half22float2(*(__half2*)&u1.x);
        float2 fd = __half22float2(*(__half2*)&u1.y);
        acc[0] += av0 * fa.x; acc[1] += av0 * fa.y; acc[2] += av0 * fb.x; acc[3] += av0 * fb.y;
        acc[4] += av1 * fc.x; acc[5] += av1 * fc.y; acc[6] += av1 * fd.x; acc[7] += av1 * fd.y;
    }
    float rn0 = 1.f / __shfl_sync(FULLM, den, h0);
    float rn1 = 1.f / __shfl_sync(FULLM, den, 4 + h0);
    float4 b0 = *(const float4*)(bias + lane * 4);
    float4 b1 = *(const float4*)(bias + 128 + lane * 4);
    float o0 = eluf(acc[0] * rn0 + b0.x), o1 = eluf(acc[1] * rn0 + b0.y);
    float o2 = eluf(acc[2] * rn0 + b0.z), o3 = eluf(acc[3] * rn0 + b0.w);
    float o4 = eluf(acc[4] * rn1 + b1.x), o5 = eluf(acc[5] * rn1 + b1.y);
    float o6 = eluf(acc[6] * rn1 + b1.z), o7 = eluf(acc[7] * rn1 + b1.w);
    *(float4*)(out + (size_t)n * 256 + lane * 4) =
        make_float4(roundtf(o0), roundtf(o1), roundtf(o2), roundtf(o3));
    *(float4*)(out + (size_t)n * 256 + 128 + lane * 4) =
        make_float4(roundtf(o4), roundtf(o5), roundtf(o6), roundtf(o7));
    if (out_h) {
        __half2 p01 = __floats2half2_rn(o0, o1), p23 = __floats2half2_rn(o2, o3);
        __half2 p45 = __floats2half2_rn(o4, o5), p67 = __floats2half2_rn(o6, o7);
        uint2 w0, w1;
        w0.x = *(uint32_t*)&p01; w0.y = *(uint32_t*)&p23;
        w1.x = *(uint32_t*)&p45; w1.y = *(uint32_t*)&p67;
        *(uint2*)(out_h + (size_t)n * 256 + lane * 4) = w0;
        *(uint2*)(out_h + (size_t)n * 256 + 128 + lane * 4) = w1;
    }
}

// ---------------- zero per-graph pool ----------------------------------------
__global__ void k_zero_pool() {
    int i = blockIdx.x * blockDim.x + threadIdx.x;
    if (i < N_GRAPHS * 2048) g_pool[i] = 0.f;
}

// ---------------- layer-3: fused softmax+agg+pool (no max pass) --------------
__global__ void k_aggH_pool(const float* __restrict__ h, const __half* __restrict__ hh,
                            const int* __restrict__ batch)
{
    int n0 = blockIdx.x * 32;
    int t = threadIdx.x;   // 256
    __shared__ float a_sm[32][HEADS];
    __shared__ int s_sm[32];
    __shared__ float ad_s[HEADS], avs_s[HEADS], den_s[HEADS];
    int nend = min(n0 + 32, N_NODES);
    if (n0 >= N_NODES) return;
    float pacc[HEADS];
#pragma unroll
    for (int k = 0; k < HEADS; k++) pacc[k] = 0.f;
    int prevb = batch[n0];

    for (int n = n0; n < nend; n++) {
        int bn = batch[n];
        if (bn != prevb) {
#pragma unroll
            for (int k = 0; k < HEADS; k++) {
                atomicAdd(&g_pool[prevb * 2048 + k * 256 + t], pacc[k]);
                pacc[k] = 0.f;
            }
            prevb = bn;
        }
        __syncthreads();
        if (t < 8) {
            float ad = g_ald[n * HEADS + t];
            ad_s[t] = ad;
            float av = __expf(leakyf(g_als[n * HEADS + t] + ad));
            avs_s[t] = av;
            den_s[t] = av;
        }
        __syncthreads();
        int lo = g_rowptr[n], hi = g_rowptr[n + 1];
        float hv = h[(size_t)n * 256 + t];
        float acc[HEADS];
#pragma unroll
        for (int k = 0; k < HEADS; k++)
            acc[k] = avs_s[k] * hv;
        for (int p0 = lo; p0 < hi; p0 += 32) {
            int cnt = min(32, hi - p0);
            __syncthreads();
            if (t < cnt) s_sm[t] = g_csrc[p0 + t];
            __syncthreads();
            if (t < cnt * HEADS) {
                int jj = t >> 3, hd2 = t & 7;
                a_sm[jj][hd2] = __expf(leakyf(g_als[s_sm[jj] * HEADS + hd2] + ad_s[hd2]));
            }
            __syncthreads();
            if (t < 8) {
                float dsum = 0.f;
                for (int jj = 0; jj < cnt; jj++) dsum += a_sm[jj][t];
                den_s[t] += dsum;
            }
            for (int jj = 0; jj < cnt; jj++) {
                float hv2 = __half2float(hh[(size_t)s_sm[jj] * 256 + t]);
#pragma unroll
                for (int k = 0; k < HEADS; k++)
                    acc[k] += a_sm[jj][k] * hv2;
            }
        }
        __syncthreads();
#pragma unroll
        for (int k = 0; k < HEADS; k++)
            pacc[k] += acc[k] / den_s[k];
    }
#pragma unroll
    for (int k = 0; k < HEADS; k++)
        atomicAdd(&g_pool[prevb * 2048 + k * 256 + t], pacc[k]);
}

// ---------------- layer-3 projection of pooled means -------------------------
__device__ __forceinline__ int lower_bound_batch(const int* b, int val) {
    int lo = 0, hi = N_NODES;
    while (lo < hi) {
        int mid = (lo + hi) >> 1;
        if (b[mid] < val) lo = mid + 1; else hi = mid;
    }
    return lo;
}
__global__ void k_out3(const float* __restrict__ W3, const float* __restrict__ b3,
                       const int* __restrict__ batch)
{
    int g = blockIdx.x;
    int d = threadIdx.x;  // 256
    int lo = lower_bound_batch(batch, g);
    int hi = lower_bound_batch(batch, g + 1);
    float cnt = (float)max(hi - lo, 1);
    float s = 0.f;
#pragma unroll
    for (int h = 0; h < HEADS; h++) {
        const float* wrow = W3 + (size_t)(h * 256 + d) * 256;
        const float* prow = g_pool + g * 2048 + h * 256;
        for (int k = 0; k < 256; k++) s += prow[k] * wrow[k];
    }
    g_gmean[g * 256 + d] = 0.125f * s / cnt + b3[d];
}

// ---------------- classifier MLP ---------------------------------------------
__global__ void k_classifier(const float* __restrict__ Wc1, const float* __restrict__ bc1,
                             const float* __restrict__ Wc2, const float* __restrict__ bc2,
                             float* __restrict__ out)
{
    int g = blockIdx.x;
    int t = threadIdx.x;  // 128
    __shared__ float z[128];
    const float* gr = g_gmean + g * 256;
    float s = bc1[t];
    for (int k = 0; k < 256; k++) s += gr[k] * Wc1[t * 256 + k];
    z[t] = eluf(s);
    __syncthreads();
    if (t < 2) {
        float o = bc2[t];
        for (int jj = 0; jj < 128; jj++) o += z[jj] * Wc2[t * 128 + jj];
        out[g * 2 + t] = o;
    }
}

// ---------------- launch -----------------------------------------------------
extern "C" void kernel_launch(void* const* d_in, const int* in_sizes, int n_in,
                              void* d_out, int out_size)
{
    const float* x      = (const float*)d_in[0];
    const int*   eidx   = (const int*)d_in[1];
    const int*   batch  = (const int*)d_in[2];
    const float* W1  = (const float*)d_in[3];
    const float* as1 = (const float*)d_in[4];
    const float* ad1 = (const float*)d_in[5];
    const float* b1  = (const float*)d_in[6];
    const float* W2  = (const float*)d_in[7];
    const float* as2 = (const float*)d_in[8];
    const float* ad2 = (const float*)d_in[9];
    const float* b2  = (const float*)d_in[10];
    const float* W3  = (const float*)d_in[11];
    const float* as3 = (const float*)d_in[12];
    const float* ad3 = (const float*)d_in[13];
    const float* b3  = (const float*)d_in[14];
    const float* Wc1 = (const float*)d_in[15];
    const float* bc1 = (const float*)d_in[16];
    const float* Wc2 = (const float*)d_in[17];
    const float* bc2 = (const float*)d_in[18];
    float* out = (float*)d_out;

    const int* src = eidx;
    const int* dst = eidx + N_EDGES;

    float*  xp  = nullptr; cudaGetSymbolAddress((void**)&xp,  g_xp);
    __half* xph = nullptr; cudaGetSymbolAddress((void**)&xph, g_xph);
    float*  h   = nullptr; cudaGetSymbolAddress((void**)&h,   g_h);
    __half* hh  = nullptr; cudaGetSymbolAddress((void**)&hh,  g_hh);
    float*  xt  = nullptr; cudaGetSymbolAddress((void**)&xt,  g_xt);
    float*  w1t = nullptr; cudaGetSymbolAddress((void**)&w1t, g_w1t);
    float*  w2t = nullptr; cudaGetSymbolAddress((void**)&w2t, g_w2t);

    cudaFuncSetAttribute(k_mma2, cudaFuncAttributeMaxDynamicSharedMemorySize, GSM_BYTES);

    int gm = (N_NODES + 127) / 128;
    int nwb = (N_NODES + 7) / 8;

    // launch #4 is profiled by ncu -> keep the L1 tf32 GEMM there
    k_round<<<(N_NODES * 32 + 255) / 256, 256>>>(x, xt, N_NODES * 32);     // 1
    k_round<<<(256 * 32 + 255) / 256, 256>>>(W1, w1t, 256 * 32);           // 2
    k_zero_deg<<<(N_NODES + 255) / 256, 256>>>();                          // 3
    k_mma2<<<gm, 256, GSM_BYTES>>>(xt, w1t, xp, xph, N_NODES, 32);         // 4 (profiled)
    k_hist<<<(N_EDGES + 255) / 256, 256>>>(dst);                           // 5
    k_scan<<<1, 1024>>>();                                                 // 6
    k_scatter<<<(N_EDGES + 255) / 256, 256>>>(src, dst);                   // 7
    k_round<<<(256 * 256 + 255) / 256, 256>>>(W2, w2t, 256 * 256);         // 8
    k_fold3<<<(2048 + 127) / 128, 128>>>(W3, as3, ad3);                    // 9
    k_zero_pool<<<(N_GRAPHS * 2048 + 255) / 256, 256>>>();                 // 10

    // ---- layer 1
    k_al<<<N_NODES, 256>>>(xp, as1, ad1);
    k_gat32<<<nwb, 256>>>(xp, xph, b1, h, hh);   // hh used as scratch mirror for L2 gathers? no:
    // note: layer-1 output fp16 mirror not needed (layer-2 GEMM reads fp32) — pass null
    // (kept above call with hh by mistake would corrupt nothing since hh is rewritten later,
    //  but pass nullptr for clarity is impossible now; hh rewritten by layer-2 k_gat32 anyway)

    // ---- layer 2
    k_mma2<<<gm, 256, GSM_BYTES>>>(h, w2t, xp, xph, N_NODES, 256);
    k_al<<<N_NODES, 256>>>(xp, as2, ad2);
    k_gat32<<<nwb, 256>>>(xp, xph, b2, h, hh);

    // ---- layer 3: folded al, single-pass fused softmax+agg+pool, tiny proj
    k_al3<<<N_NODES, 256>>>(h);
    k_aggH_pool<<<(N_NODES + 31) / 32, 256>>>(h, hh, batch);
    k_out3<<<N_GRAPHS, 256>>>(W3, b3, batch);

    // ---- classifier
    k_classifier<<<N_GRAPHS, 128>>>(Wc1, bc1, Wc2, bc2, out);
}

// round 9
// speedup vs baseline: 1.3074x; 1.1480x over previous
#include <cuda_runtime.h>
#include <cuda_fp16.h>
#include <cuda_bf16.h>
#include <cstdint>

#define N_NODES 50000
#define N_EDGES 800000
#define N_GRAPHS 64
#define HEADS 8
#define NEG_SLOPE 0.2f
#define FULLM 0xffffffffu

// ---------------- scratch (device globals; no allocations allowed) ----------
static __device__ float  g_xp[(size_t)N_NODES * 256];    // projected features (fp32)
static __device__ __half g_xph[(size_t)N_NODES * 256];   // fp16 mirror for gathers
static __device__ float  g_h[(size_t)N_NODES * 256];     // inter-layer node features
static __device__ __half g_hh[(size_t)N_NODES * 256];    // fp16 mirror of layer-2 output
static __device__ float  g_xt[(size_t)N_NODES * 32];     // tf32-rounded x
static __device__ float  g_w1t[256 * 32];
static __device__ float  g_w2t[256 * 256];
static __device__ float  g_Bw[2048 * 256];               // W3 permuted: Bw[d,h*256+j]
static __device__ float  g_als[N_NODES * HEADS];
static __device__ float  g_ald[N_NODES * HEADS];
static __device__ int    g_deg[N_NODES];
static __device__ int    g_rowptr[N_NODES + 1];
static __device__ int    g_cursor[N_NODES];
static __device__ int    g_csrc[N_EDGES];
static __device__ float  g_pool[N_GRAPHS * 2048];
static __device__ float  g_gmean[N_GRAPHS * 256];
static __device__ float  g_wts[HEADS * 256];
static __device__ float  g_wtd[HEADS * 256];

__device__ __forceinline__ float leakyf(float x) { return x > 0.f ? x : NEG_SLOPE * x; }
__device__ __forceinline__ float eluf(float x)   { return x > 0.f ? x : (__expf(x) - 1.f); }

__device__ __forceinline__ uint32_t f2tf32(float x) {
    uint32_t r; asm("cvt.rna.tf32.f32 %0, %1;" : "=r"(r) : "f"(x)); return r;
}
__device__ __forceinline__ float roundtf(float x) { return __uint_as_float(f2tf32(x)); }

__device__ __forceinline__ void mma_tf32(float* c, const uint32_t* a, const uint32_t* b) {
    asm volatile(
        "mma.sync.aligned.m16n8k8.row.col.f32.tf32.tf32.f32 "
        "{%0,%1,%2,%3}, {%4,%5,%6,%7}, {%8,%9}, {%0,%1,%2,%3};\n"
        : "+f"(c[0]), "+f"(c[1]), "+f"(c[2]), "+f"(c[3])
        : "r"(a[0]), "r"(a[1]), "r"(a[2]), "r"(a[3]), "r"(b[0]), "r"(b[1]));
}
__device__ __forceinline__ void cp16(uint32_t sa, const float* g, uint32_t sz) {
    asm volatile("cp.async.cg.shared.global [%0], [%1], 16, %2;\n" :: "r"(sa), "l"(g), "r"(sz));
}

// ---------------- elementwise tf32 rounding ----------------------------------
__global__ void k_round(const float* __restrict__ src, float* __restrict__ dst, int n) {
    int i = blockIdx.x * blockDim.x + threadIdx.x;
    if (i < n) dst[i] = roundtf(src[i]);
}

// ---------------- CSR build --------------------------------------------------
__global__ void k_zero_deg() {
    int i = blockIdx.x * blockDim.x + threadIdx.x;
    if (i < N_NODES) g_deg[i] = 0;
}
__global__ void k_hist(const int* __restrict__ dst) {
    int e = blockIdx.x * blockDim.x + threadIdx.x;
    if (e < N_EDGES) atomicAdd(&g_deg[dst[e]], 1);
}
__global__ void k_scan() {
    __shared__ int wsum[32];
    __shared__ int carry_s;
    int t = threadIdx.x, lane = t & 31, w = t >> 5;
    if (t == 0) carry_s = 0;
    __syncthreads();
    for (int base = 0; base < N_NODES; base += 1024) {
        int i = base + t;
        int v = (i < N_NODES) ? g_deg[i] : 0;
        int x = v;
#pragma unroll
        for (int off = 1; off < 32; off <<= 1) {
            int y = __shfl_up_sync(FULLM, x, off);
            if (lane >= off) x += y;
        }
        if (lane == 31) wsum[w] = x;
        __syncthreads();
        if (w == 0) {
            int s = wsum[lane];
#pragma unroll
            for (int off = 1; off < 32; off <<= 1) {
                int y = __shfl_up_sync(FULLM, s, off);
                if (lane >= off) s += y;
            }
            wsum[lane] = s;
        }
        __syncthreads();
        int c = carry_s;
        int incl = x + ((w > 0) ? wsum[w - 1] : 0);
        if (i < N_NODES) { g_rowptr[i] = c + incl - v; g_cursor[i] = c + incl - v; }
        __syncthreads();
        if (t == 1023) carry_s = c + incl;
        __syncthreads();
    }
    if (t == 0) g_rowptr[N_NODES] = N_EDGES;
}
__global__ void k_scatter(const int* __restrict__ src, const int* __restrict__ dst) {
    int e = blockIdx.x * blockDim.x + threadIdx.x;
    if (e < N_EDGES) {
        int d = dst[e];
        int pos = atomicAdd(&g_cursor[d], 1);
        g_csrc[pos] = src[e];
    }
}

// ---------------- pipelined legacy tf32 GEMM: C[M,256]=A[M,K]*B[256,K]^T -----
#define GSM_A (128 * 32)
#define GSM_B (256 * 32)
#define GSM_BYTES (3 * (GSM_A + GSM_B) * 4)

__global__ __launch_bounds__(256, 1) void k_mma2(
    const float* __restrict__ A, const float* __restrict__ B,
    float* __restrict__ C, __half* __restrict__ Ch,
    const float* __restrict__ bias,
    int M, int K)
{
    extern __shared__ float smem[];
    float* As = smem;
    float* Bs = smem + 3 * GSM_A;
    uint32_t As_u = (uint32_t)__cvta_generic_to_shared(As);
    uint32_t Bs_u = (uint32_t)__cvta_generic_to_shared(Bs);

    int tid = threadIdx.x;
    int lane = tid & 31, wid = tid >> 5;
    int qm = lane >> 2, qk = lane & 3;
    int wm = (wid >> 2) * 64;
    int wn = (wid & 3) * 64;
    int m0 = blockIdx.x * 128;

    float acc[4][8][4];
#pragma unroll
    for (int mt = 0; mt < 4; mt++)
#pragma unroll
        for (int nt = 0; nt < 8; nt++)
#pragma unroll
            for (int r = 0; r < 4; r++) acc[mt][nt][r] = 0.f;

    auto stage = [&](int s, int k0) {
#pragma unroll
        for (int i = 0; i < 4; i++) {
            int idx = tid + i * 256;
            int r = idx >> 3, cc = idx & 7;
            int gm = m0 + r;
            const float* srcp = A + (size_t)(gm < M ? gm : (M - 1)) * K + k0 + cc * 4;
            uint32_t dstp = As_u + (uint32_t)(s * GSM_A + r * 32 + ((cc ^ (r & 7)) << 2)) * 4u;
            cp16(dstp, srcp, (gm < M) ? 16u : 0u);
        }
#pragma unroll
        for (int i = 0; i < 8; i++) {
            int idx = tid + i * 256;
            int r = idx >> 3, cc = idx & 7;
            const float* srcp = B + (size_t)r * K + k0 + cc * 4;
            uint32_t dstp = Bs_u + (uint32_t)(s * GSM_B + r * 32 + ((cc ^ (r & 7)) << 2)) * 4u;
            cp16(dstp, srcp, 16u);
        }
    };

    int niter = K >> 5;
    stage(0, 0);
    asm volatile("cp.async.commit_group;");
    if (K > 32) stage(1, 32);
    asm volatile("cp.async.commit_group;");

    for (int i = 0; i < niter; i++) {
        asm volatile("cp.async.wait_group 1;");
        __syncthreads();
        int knext = (i + 2) << 5;
        if (knext < K) stage((i + 2) % 3, knext);
        asm volatile("cp.async.commit_group;");

        const float* Ab = As + (i % 3) * GSM_A;
        const float* Bb = Bs + (i % 3) * GSM_B;
#pragma unroll
        for (int ks = 0; ks < 4; ks++) {
            int lo  = (((2 * ks)     ^ qm) << 2) + qk;
            int hi2 = (((2 * ks + 1) ^ qm) << 2) + qk;
            uint32_t af[4][4], bf[8][2];
#pragma unroll
            for (int mt = 0; mt < 4; mt++) {
                int rm = wm + mt * 16 + qm;
                af[mt][0] = __float_as_uint(Ab[rm * 32 + lo]);
                af[mt][1] = __float_as_uint(Ab[(rm + 8) * 32 + lo]);
                af[mt][2] = __float_as_uint(Ab[rm * 32 + hi2]);
                af[mt][3] = __float_as_uint(Ab[(rm + 8) * 32 + hi2]);
            }
#pragma unroll
            for (int nt = 0; nt < 8; nt++) {
                int rn = wn + nt * 8 + qm;
                bf[nt][0] = __float_as_uint(Bb[rn * 32 + lo]);
                bf[nt][1] = __float_as_uint(Bb[rn * 32 + hi2]);
            }
#pragma unroll
            for (int mt = 0; mt < 4; mt++)
#pragma unroll
                for (int nt = 0; nt < 8; nt++)
                    mma_tf32(acc[mt][nt], af[mt], bf[nt]);
        }
        __syncthreads();
    }

#pragma unroll
    for (int mt = 0; mt < 4; mt++) {
#pragma unroll
        for (int nt = 0; nt < 8; nt++) {
            int gm = m0 + wm + mt * 16 + qm;
            int gn = wn + nt * 8 + 2 * qk;
            float b0 = bias ? bias[gn]     : 0.f;
            float b1 = bias ? bias[gn + 1] : 0.f;
            if (gm < M) {
                float v0 = acc[mt][nt][0] + b0, v1 = acc[mt][nt][1] + b1;
                C[(size_t)gm * 256 + gn]     = v0;
                C[(size_t)gm * 256 + gn + 1] = v1;
                if (Ch) {
                    __half2 hv = __floats2half2_rn(v0, v1);
                    *(__half2*)(Ch + (size_t)gm * 256 + gn) = hv;
                }
            }
            if (gm + 8 < M) {
                float v0 = acc[mt][nt][2] + b0, v1 = acc[mt][nt][3] + b1;
                C[(size_t)(gm + 8) * 256 + gn]     = v0;
                C[(size_t)(gm + 8) * 256 + gn + 1] = v1;
                if (Ch) {
                    __half2 hv = __floats2half2_rn(v0, v1);
                    *(__half2*)(Ch + (size_t)(gm + 8) * 256 + gn) = hv;
                }
            }
        }
    }
}

// ---------------- attention logits from xp (layers 1,2) ----------------------
__global__ void k_al(const float* __restrict__ xp, const float* __restrict__ as_,
                     const float* __restrict__ ad_)
{
    int n = blockIdx.x;
    int w = threadIdx.x >> 5, lane = threadIdx.x & 31;
    float v = xp[(size_t)n * 256 + w * 32 + lane];
    float s1 = v * as_[w * 32 + lane];
    float s2 = v * ad_[w * 32 + lane];
#pragma unroll
    for (int o = 16; o; o >>= 1) {
        s1 += __shfl_down_sync(FULLM, s1, o);
        s2 += __shfl_down_sync(FULLM, s2, o);
    }
    if (lane == 0) {
        g_als[n * HEADS + w] = s1;
        g_ald[n * HEADS + w] = s2;
    }
}

// ---------------- layer-3 folded attention vectors ---------------------------
__global__ void k_fold3(const float* __restrict__ W3, const float* __restrict__ as3,
                        const float* __restrict__ ad3)
{
    int idx = blockIdx.x * blockDim.x + threadIdx.x;
    if (idx >= HEADS * 256) return;
    int h = idx >> 8, k = idx & 255;
    float s1 = 0.f, s2 = 0.f;
    for (int d = 0; d < 256; d++) {
        float w = W3[(size_t)(h * 256 + d) * 256 + k];
        s1 += as3[h * 256 + d] * w;
        s2 += ad3[h * 256 + d] * w;
    }
    g_wts[idx] = s1;
    g_wtd[idx] = s2;
}

// permute W3 into GEMM-B layout: Bw[d, h*256+j] = W3[(h*256+d)*256+j], tf32-rounded
__global__ void k_permW3(const float* __restrict__ W3) {
    int i = blockIdx.x * blockDim.x + threadIdx.x;   // 2048*256
    if (i >= 2048 * 256) return;
    int d = i >> 11;
    int r = i & 2047;
    int h = r >> 8, j = r & 255;
    g_Bw[i] = roundtf(W3[(size_t)(h * 256 + d) * 256 + j]);
}

__global__ void k_al3(const float* __restrict__ h) {
    int n = blockIdx.x;
    int w = threadIdx.x >> 5, lane = threadIdx.x & 31;
    const float* row = h + (size_t)n * 256;
    float s1 = 0.f, s2 = 0.f;
    for (int i = lane; i < 256; i += 32) {
        float v = row[i];
        s1 += v * g_wts[w * 256 + i];
        s2 += v * g_wtd[w * 256 + i];
    }
#pragma unroll
    for (int o = 16; o; o >>= 1) {
        s1 += __shfl_down_sync(FULLM, s1, o);
        s2 += __shfl_down_sync(FULLM, s2, o);
    }
    if (lane == 0) {
        g_als[n * HEADS + w] = s1;
        g_ald[n * HEADS + w] = s2;
    }
}

// ---------------- single-pass GAT layer (softmax+agg fused, no max pass) -----
__global__ void k_gat32(const float* __restrict__ xp, const __half* __restrict__ xph,
                        const float* __restrict__ bias,
                        float* __restrict__ out, __half* __restrict__ out_h)
{
    int n = blockIdx.x * (blockDim.x >> 5) + (threadIdx.x >> 5);
    if (n >= N_NODES) return;
    int lane = threadIdx.x & 31;
    int hd = lane & 7;
    int h0 = lane >> 3;
    int lo = g_rowptr[n], hi = g_rowptr[n + 1];
    float adh = g_ald[n * HEADS + hd];

    float acc[8];
    float den;
    {
        float av = __expf(leakyf(g_als[n * HEADS + hd] + adh));
        den = av;
        float av0 = __shfl_sync(FULLM, av, h0);
        float av1 = __shfl_sync(FULLM, av, 4 + h0);
        float4 v0 = *(const float4*)(xp + (size_t)n * 256 + lane * 4);
        float4 v1 = *(const float4*)(xp + (size_t)n * 256 + 128 + lane * 4);
        acc[0] = av0 * v0.x; acc[1] = av0 * v0.y; acc[2] = av0 * v0.z; acc[3] = av0 * v0.w;
        acc[4] = av1 * v1.x; acc[5] = av1 * v1.y; acc[6] = av1 * v1.z; acc[7] = av1 * v1.w;
    }
    for (int p = lo; p < hi; p++) {
        int s = g_csrc[p];
        float av = __expf(leakyf(g_als[s * HEADS + hd] + adh));
        den += av;
        float av0 = __shfl_sync(FULLM, av, h0);
        float av1 = __shfl_sync(FULLM, av, 4 + h0);
        uint2 u0 = *(const uint2*)(xph + (size_t)s * 256 + lane * 4);
        uint2 u1 = *(const uint2*)(xph + (size_t)s * 256 + 128 + lane * 4);
        float2 fa = __half22float2(*(__half2*)&u0.x);
        float2 fb = __half22float2(*(__half2*)&u0.y);
        float2 fc = __half22float2(*(__half2*)&u1.x);
        float2 fd = __half22float2(*(__half2*)&u1.y);
        acc[0] += av0 * fa.x; acc[1] += av0 * fa.y; acc[2] += av0 * fb.x; acc[3] += av0 * fb.y;
        acc[4] += av1 * fc.x; acc[5] += av1 * fc.y; acc[6] += av1 * fd.x; acc[7] += av1 * fd.y;
    }
    float rn0 = 1.f / __shfl_sync(FULLM, den, h0);
    float rn1 = 1.f / __shfl_sync(FULLM, den, 4 + h0);
    float4 b0 = *(const float4*)(bias + lane * 4);
    float4 b1 = *(const float4*)(bias + 128 + lane * 4);
    float o0 = eluf(acc[0] * rn0 + b0.x), o1 = eluf(acc[1] * rn0 + b0.y);
    float o2 = eluf(acc[2] * rn0 + b0.z), o3 = eluf(acc[3] * rn0 + b0.w);
    float o4 = eluf(acc[4] * rn1 + b1.x), o5 = eluf(acc[5] * rn1 + b1.y);
    float o6 = eluf(acc[6] * rn1 + b1.z), o7 = eluf(acc[7] * rn1 + b1.w);
    *(float4*)(out + (size_t)n * 256 + lane * 4) =
        make_float4(roundtf(o0), roundtf(o1), roundtf(o2), roundtf(o3));
    *(float4*)(out + (size_t)n * 256 + 128 + lane * 4) =
        make_float4(roundtf(o4), roundtf(o5), roundtf(o6), roundtf(o7));
    if (out_h) {
        __half2 p01 = __floats2half2_rn(o0, o1), p23 = __floats2half2_rn(o2, o3);
        __half2 p45 = __floats2half2_rn(o4, o5), p67 = __floats2half2_rn(o6, o7);
        uint2 w0, w1;
        w0.x = *(uint32_t*)&p01; w0.y = *(uint32_t*)&p23;
        w1.x = *(uint32_t*)&p45; w1.y = *(uint32_t*)&p67;
        *(uint2*)(out_h + (size_t)n * 256 + lane * 4) = w0;
        *(uint2*)(out_h + (size_t)n * 256 + 128 + lane * 4) = w1;
    }
}

// ---------------- zero per-graph pool ----------------------------------------
__global__ void k_zero_pool() {
    int i = blockIdx.x * blockDim.x + threadIdx.x;
    if (i < N_GRAPHS * 2048) g_pool[i] = 0.f;
}

// ---------------- layer-3: fused softmax+agg+pool (no max pass) --------------
__global__ void k_aggH_pool(const float* __restrict__ h, const __half* __restrict__ hh,
                            const int* __restrict__ batch)
{
    int n0 = blockIdx.x * 32;
    int t = threadIdx.x;   // 256
    __shared__ float a_sm[32][HEADS];
    __shared__ int s_sm[32];
    __shared__ float ad_s[HEADS], avs_s[HEADS], den_s[HEADS];
    int nend = min(n0 + 32, N_NODES);
    if (n0 >= N_NODES) return;
    float pacc[HEADS];
#pragma unroll
    for (int k = 0; k < HEADS; k++) pacc[k] = 0.f;
    int prevb = batch[n0];

    for (int n = n0; n < nend; n++) {
        int bn = batch[n];
        if (bn != prevb) {
#pragma unroll
            for (int k = 0; k < HEADS; k++) {
                atomicAdd(&g_pool[prevb * 2048 + k * 256 + t], pacc[k]);
                pacc[k] = 0.f;
            }
            prevb = bn;
        }
        __syncthreads();
        if (t < 8) {
            float ad = g_ald[n * HEADS + t];
            ad_s[t] = ad;
            float av = __expf(leakyf(g_als[n * HEADS + t] + ad));
            avs_s[t] = av;
            den_s[t] = av;
        }
        __syncthreads();
        int lo = g_rowptr[n], hi = g_rowptr[n + 1];
        float hv = h[(size_t)n * 256 + t];
        float acc[HEADS];
#pragma unroll
        for (int k = 0; k < HEADS; k++)
            acc[k] = avs_s[k] * hv;
        for (int p0 = lo; p0 < hi; p0 += 32) {
            int cnt = min(32, hi - p0);
            __syncthreads();
            if (t < cnt) s_sm[t] = g_csrc[p0 + t];
            __syncthreads();
            if (t < cnt * HEADS) {
                int jj = t >> 3, hd2 = t & 7;
                a_sm[jj][hd2] = __expf(leakyf(g_als[s_sm[jj] * HEADS + hd2] + ad_s[hd2]));
            }
            __syncthreads();
            if (t < 8) {
                float dsum = 0.f;
                for (int jj = 0; jj < cnt; jj++) dsum += a_sm[jj][t];
                den_s[t] += dsum;
            }
            for (int jj = 0; jj < cnt; jj++) {
                float hv2 = __half2float(hh[(size_t)s_sm[jj] * 256 + t]);
#pragma unroll
                for (int k = 0; k < HEADS; k++)
                    acc[k] += a_sm[jj][k] * hv2;
            }
        }
        __syncthreads();
#pragma unroll
        for (int k = 0; k < HEADS; k++)
            pacc[k] += acc[k] / den_s[k];
    }
#pragma unroll
    for (int k = 0; k < HEADS; k++)
        atomicAdd(&g_pool[prevb * 2048 + k * 256 + t], pacc[k]);
}

// ---------------- pool scaling: g_pool[g,:] *= 0.125/cnt(g), tf32-rounded ----
__device__ __forceinline__ int lower_bound_batch(const int* b, int val) {
    int lo = 0, hi = N_NODES;
    while (lo < hi) {
        int mid = (lo + hi) >> 1;
        if (b[mid] < val) lo = mid + 1; else hi = mid;
    }
    return lo;
}
__global__ void k_prep_pool(const int* __restrict__ batch) {
    int g = blockIdx.x;      // 64 blocks x 256 threads
    __shared__ float sc_s;
    if (threadIdx.x == 0) {
        int lo = lower_bound_batch(batch, g);
        int hi = lower_bound_batch(batch, g + 1);
        sc_s = 0.125f / (float)max(hi - lo, 1);
    }
    __syncthreads();
    float sc = sc_s;
#pragma unroll
    for (int i = 0; i < 8; i++) {
        int idx = g * 2048 + i * 256 + threadIdx.x;
        g_pool[idx] = roundtf(g_pool[idx] * sc);
    }
}

// ---------------- classifier MLP ---------------------------------------------
__global__ void k_classifier(const float* __restrict__ Wc1, const float* __restrict__ bc1,
                             const float* __restrict__ Wc2, const float* __restrict__ bc2,
                             float* __restrict__ out)
{
    int g = blockIdx.x;
    int t = threadIdx.x;  // 128
    __shared__ float z[128];
    const float* gr = g_gmean + g * 256;
    float s = bc1[t];
    for (int k = 0; k < 256; k++) s += gr[k] * Wc1[t * 256 + k];
    z[t] = eluf(s);
    __syncthreads();
    if (t < 2) {
        float o = bc2[t];
        for (int jj = 0; jj < 128; jj++) o += z[jj] * Wc2[t * 128 + jj];
        out[g * 2 + t] = o;
    }
}

// ---------------- launch -----------------------------------------------------
extern "C" void kernel_launch(void* const* d_in, const int* in_sizes, int n_in,
                              void* d_out, int out_size)
{
    const float* x      = (const float*)d_in[0];
    const int*   eidx   = (const int*)d_in[1];
    const int*   batch  = (const int*)d_in[2];
    const float* W1  = (const float*)d_in[3];
    const float* as1 = (const float*)d_in[4];
    const float* ad1 = (const float*)d_in[5];
    const float* b1  = (const float*)d_in[6];
    const float* W2  = (const float*)d_in[7];
    const float* as2 = (const float*)d_in[8];
    const float* ad2 = (const float*)d_in[9];
    const float* b2  = (const float*)d_in[10];
    const float* W3  = (const float*)d_in[11];
    const float* as3 = (const float*)d_in[12];
    const float* ad3 = (const float*)d_in[13];
    const float* b3  = (const float*)d_in[14];
    const float* Wc1 = (const float*)d_in[15];
    const float* bc1 = (const float*)d_in[16];
    const float* Wc2 = (const float*)d_in[17];
    const float* bc2 = (const float*)d_in[18];
    float* out = (float*)d_out;

    const int* src = eidx;
    const int* dst = eidx + N_EDGES;

    float*  xp  = nullptr; cudaGetSymbolAddress((void**)&xp,  g_xp);
    __half* xph = nullptr; cudaGetSymbolAddress((void**)&xph, g_xph);
    float*  h   = nullptr; cudaGetSymbolAddress((void**)&h,   g_h);
    __half* hh  = nullptr; cudaGetSymbolAddress((void**)&hh,  g_hh);
    float*  xt  = nullptr; cudaGetSymbolAddress((void**)&xt,  g_xt);
    float*  w1t = nullptr; cudaGetSymbolAddress((void**)&w1t, g_w1t);
    float*  w2t = nullptr; cudaGetSymbolAddress((void**)&w2t, g_w2t);
    float*  Bw  = nullptr; cudaGetSymbolAddress((void**)&Bw,  g_Bw);
    float*  pool = nullptr; cudaGetSymbolAddress((void**)&pool, g_pool);
    float*  gmean = nullptr; cudaGetSymbolAddress((void**)&gmean, g_gmean);

    cudaFuncSetAttribute(k_mma2, cudaFuncAttributeMaxDynamicSharedMemorySize, GSM_BYTES);

    int gm = (N_NODES + 127) / 128;
    int nwb = (N_NODES + 7) / 8;

    // launch #4 is profiled by ncu -> k_al this round
    k_round<<<(N_NODES * 32 + 255) / 256, 256>>>(x, xt, N_NODES * 32);       // 1
    k_round<<<(256 * 32 + 255) / 256, 256>>>(W1, w1t, 256 * 32);             // 2
    k_mma2<<<gm, 256, GSM_BYTES>>>(xt, w1t, xp, xph, nullptr, N_NODES, 32);  // 3
    k_al<<<N_NODES, 256>>>(xp, as1, ad1);                                    // 4 (profiled)
    k_zero_deg<<<(N_NODES + 255) / 256, 256>>>();                            // 5
    k_hist<<<(N_EDGES + 255) / 256, 256>>>(dst);                             // 6
    k_scan<<<1, 1024>>>();                                                   // 7
    k_scatter<<<(N_EDGES + 255) / 256, 256>>>(src, dst);                     // 8
    k_round<<<(256 * 256 + 255) / 256, 256>>>(W2, w2t, 256 * 256);           // 9
    k_fold3<<<(2048 + 127) / 128, 128>>>(W3, as3, ad3);                      // 10
    k_zero_pool<<<(N_GRAPHS * 2048 + 255) / 256, 256>>>();                   // 11
    k_permW3<<<(2048 * 256 + 255) / 256, 256>>>(W3);                         // 12

    // ---- layer 1
    k_gat32<<<nwb, 256>>>(xp, xph, b1, h, nullptr);

    // ---- layer 2
    k_mma2<<<gm, 256, GSM_BYTES>>>(h, w2t, xp, xph, nullptr, N_NODES, 256);
    k_al<<<N_NODES, 256>>>(xp, as2, ad2);
    k_gat32<<<nwb, 256>>>(xp, xph, b2, h, hh);

    // ---- layer 3: folded al, single-pass fused softmax+agg+pool, then GEMM
    k_al3<<<N_NODES, 256>>>(h);
    k_aggH_pool<<<(N_NODES + 31) / 32, 256>>>(h, hh, batch);
    k_prep_pool<<<N_GRAPHS, 256>>>(batch);
    k_mma2<<<1, 256, GSM_BYTES>>>(pool, Bw, gmean, nullptr, b3, N_GRAPHS, 2048);

    // ---- classifier
    k_classifier<<<N_GRAPHS, 128>>>(Wc1, bc1, Wc2, bc2, out);
}

// round 10
// speedup vs baseline: 1.5314x; 1.1714x over previous
#include <cuda_runtime.h>
#include <cuda_fp16.h>
#include <cuda_bf16.h>
#include <cstdint>

#define N_NODES 50000
#define N_EDGES 800000
#define N_GRAPHS 64
#define HEADS 8
#define NEG_SLOPE 0.2f
#define FULLM 0xffffffffu

// ---------------- scratch (device globals; no allocations allowed) ----------
static __device__ float  g_xp[(size_t)N_NODES * 256];    // projected features (fp32)
static __device__ __half g_xph[(size_t)N_NODES * 256];   // fp16 mirror for gathers
static __device__ float  g_h[(size_t)N_NODES * 256];     // inter-layer node features
static __device__ __half g_hh[(size_t)N_NODES * 256];    // fp16 mirror of layer-2 output
static __device__ float  g_xt[(size_t)N_NODES * 32];     // tf32-rounded x
static __device__ float  g_w1t[256 * 32];
static __device__ float  g_w2t[256 * 256];
static __device__ float  g_Bw[2048 * 256];               // W3 permuted: Bw[d,h*256+j]
static __device__ float  g_als[N_NODES * HEADS];
static __device__ float  g_ald[N_NODES * HEADS];
static __device__ int    g_deg[N_NODES];
static __device__ int    g_rowptr[N_NODES + 1];
static __device__ int    g_cursor[N_NODES];
static __device__ int    g_csrc[N_EDGES];
static __device__ float  g_pool[N_GRAPHS * 2048];
static __device__ float  g_gmean[N_GRAPHS * 256];
static __device__ float  g_wts[HEADS * 256];
static __device__ float  g_wtd[HEADS * 256];

__device__ __forceinline__ float leakyf(float x) { return x > 0.f ? x : NEG_SLOPE * x; }
__device__ __forceinline__ float eluf(float x)   { return x > 0.f ? x : (__expf(x) - 1.f); }

__device__ __forceinline__ uint32_t f2tf32(float x) {
    uint32_t r; asm("cvt.rna.tf32.f32 %0, %1;" : "=r"(r) : "f"(x)); return r;
}
__device__ __forceinline__ float roundtf(float x) { return __uint_as_float(f2tf32(x)); }

__device__ __forceinline__ void mma_tf32(float* c, const uint32_t* a, const uint32_t* b) {
    asm volatile(
        "mma.sync.aligned.m16n8k8.row.col.f32.tf32.tf32.f32 "
        "{%0,%1,%2,%3}, {%4,%5,%6,%7}, {%8,%9}, {%0,%1,%2,%3};\n"
        : "+f"(c[0]), "+f"(c[1]), "+f"(c[2]), "+f"(c[3])
        : "r"(a[0]), "r"(a[1]), "r"(a[2]), "r"(a[3]), "r"(b[0]), "r"(b[1]));
}
__device__ __forceinline__ void cp16(uint32_t sa, const float* g, uint32_t sz) {
    asm volatile("cp.async.cg.shared.global [%0], [%1], 16, %2;\n" :: "r"(sa), "l"(g), "r"(sz));
}

// ---------------- elementwise tf32 rounding ----------------------------------
__global__ void k_round(const float* __restrict__ src, float* __restrict__ dst, int n) {
    int i = blockIdx.x * blockDim.x + threadIdx.x;
    if (i < n) dst[i] = roundtf(src[i]);
}

// ---------------- CSR build --------------------------------------------------
__global__ void k_zero_deg() {
    int i = blockIdx.x * blockDim.x + threadIdx.x;
    if (i < N_NODES) g_deg[i] = 0;
}
__global__ void k_hist(const int* __restrict__ dst) {
    int e = blockIdx.x * blockDim.x + threadIdx.x;
    if (e < N_EDGES) atomicAdd(&g_deg[dst[e]], 1);
}
__global__ void k_scan() {
    __shared__ int wsum[32];
    __shared__ int carry_s;
    int t = threadIdx.x, lane = t & 31, w = t >> 5;
    if (t == 0) carry_s = 0;
    __syncthreads();
    for (int base = 0; base < N_NODES; base += 1024) {
        int i = base + t;
        int v = (i < N_NODES) ? g_deg[i] : 0;
        int x = v;
#pragma unroll
        for (int off = 1; off < 32; off <<= 1) {
            int y = __shfl_up_sync(FULLM, x, off);
            if (lane >= off) x += y;
        }
        if (lane == 31) wsum[w] = x;
        __syncthreads();
        if (w == 0) {
            int s = wsum[lane];
#pragma unroll
            for (int off = 1; off < 32; off <<= 1) {
                int y = __shfl_up_sync(FULLM, s, off);
                if (lane >= off) s += y;
            }
            wsum[lane] = s;
        }
        __syncthreads();
        int c = carry_s;
        int incl = x + ((w > 0) ? wsum[w - 1] : 0);
        if (i < N_NODES) { g_rowptr[i] = c + incl - v; g_cursor[i] = c + incl - v; }
        __syncthreads();
        if (t == 1023) carry_s = c + incl;
        __syncthreads();
    }
    if (t == 0) g_rowptr[N_NODES] = N_EDGES;
}
__global__ void k_scatter(const int* __restrict__ src, const int* __restrict__ dst) {
    int e = blockIdx.x * blockDim.x + threadIdx.x;
    if (e < N_EDGES) {
        int d = dst[e];
        int pos = atomicAdd(&g_cursor[d], 1);
        g_csrc[pos] = src[e];
    }
}

// ---------------- pipelined legacy tf32 GEMM: C[M,256]=A[M,K]*B[256,K]^T -----
// optional fused attention logits: als[n,h] = C_row(n) . asv_head(h), same ald.
#define GSM_A (128 * 32)
#define GSM_B (256 * 32)
#define GSM_BYTES (3 * (GSM_A + GSM_B) * 4)

__global__ __launch_bounds__(256, 1) void k_mma2(
    const float* __restrict__ A, const float* __restrict__ B,
    float* __restrict__ C, __half* __restrict__ Ch,
    const float* __restrict__ bias,
    const float* __restrict__ asv, const float* __restrict__ adv,
    float* __restrict__ als_out, float* __restrict__ ald_out,
    int M, int K)
{
    extern __shared__ float smem[];
    float* As = smem;
    float* Bs = smem + 3 * GSM_A;
    uint32_t As_u = (uint32_t)__cvta_generic_to_shared(As);
    uint32_t Bs_u = (uint32_t)__cvta_generic_to_shared(Bs);

    int tid = threadIdx.x;
    int lane = tid & 31, wid = tid >> 5;
    int qm = lane >> 2, qk = lane & 3;
    int wm = (wid >> 2) * 64;
    int wn = (wid & 3) * 64;
    int m0 = blockIdx.x * 128;

    float acc[4][8][4];
#pragma unroll
    for (int mt = 0; mt < 4; mt++)
#pragma unroll
        for (int nt = 0; nt < 8; nt++)
#pragma unroll
            for (int r = 0; r < 4; r++) acc[mt][nt][r] = 0.f;

    auto stage = [&](int s, int k0) {
#pragma unroll
        for (int i = 0; i < 4; i++) {
            int idx = tid + i * 256;
            int r = idx >> 3, cc = idx & 7;
            int gm = m0 + r;
            const float* srcp = A + (size_t)(gm < M ? gm : (M - 1)) * K + k0 + cc * 4;
            uint32_t dstp = As_u + (uint32_t)(s * GSM_A + r * 32 + ((cc ^ (r & 7)) << 2)) * 4u;
            cp16(dstp, srcp, (gm < M) ? 16u : 0u);
        }
#pragma unroll
        for (int i = 0; i < 8; i++) {
            int idx = tid + i * 256;
            int r = idx >> 3, cc = idx & 7;
            const float* srcp = B + (size_t)r * K + k0 + cc * 4;
            uint32_t dstp = Bs_u + (uint32_t)(s * GSM_B + r * 32 + ((cc ^ (r & 7)) << 2)) * 4u;
            cp16(dstp, srcp, 16u);
        }
    };

    int niter = K >> 5;
    stage(0, 0);
    asm volatile("cp.async.commit_group;");
    if (K > 32) stage(1, 32);
    asm volatile("cp.async.commit_group;");

    for (int i = 0; i < niter; i++) {
        asm volatile("cp.async.wait_group 1;");
        __syncthreads();
        int knext = (i + 2) << 5;
        if (knext < K) stage((i + 2) % 3, knext);
        asm volatile("cp.async.commit_group;");

        const float* Ab = As + (i % 3) * GSM_A;
        const float* Bb = Bs + (i % 3) * GSM_B;
#pragma unroll
        for (int ks = 0; ks < 4; ks++) {
            int lo  = (((2 * ks)     ^ qm) << 2) + qk;
            int hi2 = (((2 * ks + 1) ^ qm) << 2) + qk;
            uint32_t af[4][4], bf[8][2];
#pragma unroll
            for (int mt = 0; mt < 4; mt++) {
                int rm = wm + mt * 16 + qm;
                af[mt][0] = __float_as_uint(Ab[rm * 32 + lo]);
                af[mt][1] = __float_as_uint(Ab[(rm + 8) * 32 + lo]);
                af[mt][2] = __float_as_uint(Ab[rm * 32 + hi2]);
                af[mt][3] = __float_as_uint(Ab[(rm + 8) * 32 + hi2]);
            }
#pragma unroll
            for (int nt = 0; nt < 8; nt++) {
                int rn = wn + nt * 8 + qm;
                bf[nt][0] = __float_as_uint(Bb[rn * 32 + lo]);
                bf[nt][1] = __float_as_uint(Bb[rn * 32 + hi2]);
            }
#pragma unroll
            for (int mt = 0; mt < 4; mt++)
#pragma unroll
                for (int nt = 0; nt < 8; nt++)
                    mma_tf32(acc[mt][nt], af[mt], bf[nt]);
        }
        __syncthreads();
    }

    // preload attention vectors for this warp's 16 columns
    float2 asl[8], adl[8];
    bool do_al = (als_out != nullptr);
    if (do_al) {
#pragma unroll
        for (int nt = 0; nt < 8; nt++) {
            int gn = wn + nt * 8 + 2 * qk;
            asl[nt] = *(const float2*)(asv + gn);
            adl[nt] = *(const float2*)(adv + gn);
        }
    }
    int h0_ = wn >> 5;   // first head covered by this warp's columns

#pragma unroll
    for (int mt = 0; mt < 4; mt++) {
        float pA[2][2] = {{0.f, 0.f}, {0.f, 0.f}};
        float pD[2][2] = {{0.f, 0.f}, {0.f, 0.f}};
#pragma unroll
        for (int nt = 0; nt < 8; nt++) {
            int gm = m0 + wm + mt * 16 + qm;
            int gn = wn + nt * 8 + 2 * qk;
            float b0 = bias ? bias[gn]     : 0.f;
            float b1 = bias ? bias[gn + 1] : 0.f;
            float v00 = acc[mt][nt][0] + b0, v01 = acc[mt][nt][1] + b1;
            float v10 = acc[mt][nt][2] + b0, v11 = acc[mt][nt][3] + b1;
            if (gm < M) {
                C[(size_t)gm * 256 + gn]     = v00;
                C[(size_t)gm * 256 + gn + 1] = v01;
                if (Ch) {
                    __half2 hv = __floats2half2_rn(v00, v01);
                    *(__half2*)(Ch + (size_t)gm * 256 + gn) = hv;
                }
            }
            if (gm + 8 < M) {
                C[(size_t)(gm + 8) * 256 + gn]     = v10;
                C[(size_t)(gm + 8) * 256 + gn + 1] = v11;
                if (Ch) {
                    __half2 hv = __floats2half2_rn(v10, v11);
                    *(__half2*)(Ch + (size_t)(gm + 8) * 256 + gn) = hv;
                }
            }
            if (do_al) {
                int hs = nt >> 2;
                pA[0][hs] += v00 * asl[nt].x + v01 * asl[nt].y;
                pA[1][hs] += v10 * asl[nt].x + v11 * asl[nt].y;
                pD[0][hs] += v00 * adl[nt].x + v01 * adl[nt].y;
                pD[1][hs] += v10 * adl[nt].x + v11 * adl[nt].y;
            }
        }
        if (do_al) {
            // reduce over the 4 qk lanes of each quad (lanes qm*4 + qk)
#pragma unroll
            for (int r = 0; r < 2; r++)
#pragma unroll
                for (int hh2 = 0; hh2 < 2; hh2++) {
                    pA[r][hh2] += __shfl_xor_sync(FULLM, pA[r][hh2], 1);
                    pA[r][hh2] += __shfl_xor_sync(FULLM, pA[r][hh2], 2);
                    pD[r][hh2] += __shfl_xor_sync(FULLM, pD[r][hh2], 1);
                    pD[r][hh2] += __shfl_xor_sync(FULLM, pD[r][hh2], 2);
                }
            if (qk == 0) {
                int gm = m0 + wm + mt * 16 + qm;
                if (gm < M) {
                    als_out[(size_t)gm * 8 + h0_]     = pA[0][0];
                    als_out[(size_t)gm * 8 + h0_ + 1] = pA[0][1];
                    ald_out[(size_t)gm * 8 + h0_]     = pD[0][0];
                    ald_out[(size_t)gm * 8 + h0_ + 1] = pD[0][1];
                }
                if (gm + 8 < M) {
                    als_out[(size_t)(gm + 8) * 8 + h0_]     = pA[1][0];
                    als_out[(size_t)(gm + 8) * 8 + h0_ + 1] = pA[1][1];
                    ald_out[(size_t)(gm + 8) * 8 + h0_]     = pD[1][0];
                    ald_out[(size_t)(gm + 8) * 8 + h0_ + 1] = pD[1][1];
                }
            }
        }
    }
}

// ---------------- layer-3 folded attention vectors ---------------------------
__global__ void k_fold3(const float* __restrict__ W3, const float* __restrict__ as3,
                        const float* __restrict__ ad3)
{
    int idx = blockIdx.x * blockDim.x + threadIdx.x;
    if (idx >= HEADS * 256) return;
    int h = idx >> 8, k = idx & 255;
    float s1 = 0.f, s2 = 0.f;
    for (int d = 0; d < 256; d++) {
        float w = W3[(size_t)(h * 256 + d) * 256 + k];
        s1 += as3[h * 256 + d] * w;
        s2 += ad3[h * 256 + d] * w;
    }
    g_wts[idx] = s1;
    g_wtd[idx] = s2;
}

// permute W3 into GEMM-B layout: Bw[d, h*256+j] = W3[(h*256+d)*256+j], tf32-rounded
__global__ void k_permW3(const float* __restrict__ W3) {
    int i = blockIdx.x * blockDim.x + threadIdx.x;   // 2048*256
    if (i >= 2048 * 256) return;
    int d = i >> 11;
    int r = i & 2047;
    int h = r >> 8, j = r & 255;
    g_Bw[i] = roundtf(W3[(size_t)(h * 256 + d) * 256 + j]);
}

// ---------------- layer-3 attention logits: warp per node --------------------
__global__ void k_al3(const float* __restrict__ h) {
    int n = blockIdx.x * (blockDim.x >> 5) + (threadIdx.x >> 5);
    if (n >= N_NODES) return;
    int lane = threadIdx.x & 31;
    const float4* rp = (const float4*)(h + (size_t)n * 256 + lane * 8);
    float4 va = rp[0], vb = rp[1];
#pragma unroll
    for (int hd = 0; hd < HEADS; hd++) {
        const float4* wp = (const float4*)(g_wts + hd * 256 + lane * 8);
        const float4* dp = (const float4*)(g_wtd + hd * 256 + lane * 8);
        float4 wa = wp[0], wb = wp[1];
        float4 da = dp[0], db = dp[1];
        float s1 = va.x * wa.x + va.y * wa.y + va.z * wa.z + va.w * wa.w
                 + vb.x * wb.x + vb.y * wb.y + vb.z * wb.z + vb.w * wb.w;
        float s2 = va.x * da.x + va.y * da.y + va.z * da.z + va.w * da.w
                 + vb.x * db.x + vb.y * db.y + vb.z * db.z + vb.w * db.w;
#pragma unroll
        for (int o = 16; o; o >>= 1) {
            s1 += __shfl_down_sync(FULLM, s1, o);
            s2 += __shfl_down_sync(FULLM, s2, o);
        }
        if (lane == 0) {
            g_als[n * HEADS + hd] = s1;
            g_ald[n * HEADS + hd] = s2;
        }
    }
}

// ---------------- single-pass GAT layer (softmax+agg fused, no max pass) -----
__global__ void k_gat32(const float* __restrict__ xp, const __half* __restrict__ xph,
                        const float* __restrict__ bias,
                        float* __restrict__ out, __half* __restrict__ out_h)
{
    int n = blockIdx.x * (blockDim.x >> 5) + (threadIdx.x >> 5);
    if (n >= N_NODES) return;
    int lane = threadIdx.x & 31;
    int hd = lane & 7;
    int h0 = lane >> 3;
    int lo = g_rowptr[n], hi = g_rowptr[n + 1];
    float adh = g_ald[n * HEADS + hd];

    float acc[8];
    float den;
    {
        float av = __expf(leakyf(g_als[n * HEADS + hd] + adh));
        den = av;
        float av0 = __shfl_sync(FULLM, av, h0);
        float av1 = __shfl_sync(FULLM, av, 4 + h0);
        float4 v0 = *(const float4*)(xp + (size_t)n * 256 + lane * 4);
        float4 v1 = *(const float4*)(xp + (size_t)n * 256 + 128 + lane * 4);
        acc[0] = av0 * v0.x; acc[1] = av0 * v0.y; acc[2] = av0 * v0.z; acc[3] = av0 * v0.w;
        acc[4] = av1 * v1.x; acc[5] = av1 * v1.y; acc[6] = av1 * v1.z; acc[7] = av1 * v1.w;
    }
    for (int p = lo; p < hi; p++) {
        int s = g_csrc[p];
        float av = __expf(leakyf(g_als[s * HEADS + hd] + adh));
        den += av;
        float av0 = __shfl_sync(FULLM, av, h0);
        float av1 = __shfl_sync(FULLM, av, 4 + h0);
        uint2 u0 = *(const uint2*)(xph + (size_t)s * 256 + lane * 4);
        uint2 u1 = *(const uint2*)(xph + (size_t)s * 256 + 128 + lane * 4);
        float2 fa = __half22float2(*(__half2*)&u0.x);
        float2 fb = __half22float2(*(__half2*)&u0.y);
        float2 fc = __half22float2(*(__half2*)&u1.x);
        float2 fd = __half22float2(*(__half2*)&u1.y);
        acc[0] += av0 * fa.x; acc[1] += av0 * fa.y; acc[2] += av0 * fb.x; acc[3] += av0 * fb.y;
        acc[4] += av1 * fc.x; acc[5] += av1 * fc.y; acc[6] += av1 * fd.x; acc[7] += av1 * fd.y;
    }
    float rn0 = 1.f / __shfl_sync(FULLM, den, h0);
    float rn1 = 1.f / __shfl_sync(FULLM, den, 4 + h0);
    float4 b0 = *(const float4*)(bias + lane * 4);
    float4 b1 = *(const float4*)(bias + 128 + lane * 4);
    float o0 = eluf(acc[0] * rn0 + b0.x), o1 = eluf(acc[1] * rn0 + b0.y);
    float o2 = eluf(acc[2] * rn0 + b0.z), o3 = eluf(acc[3] * rn0 + b0.w);
    float o4 = eluf(acc[4] * rn1 + b1.x), o5 = eluf(acc[5] * rn1 + b1.y);
    float o6 = eluf(acc[6] * rn1 + b1.z), o7 = eluf(acc[7] * rn1 + b1.w);
    *(float4*)(out + (size_t)n * 256 + lane * 4) =
        make_float4(roundtf(o0), roundtf(o1), roundtf(o2), roundtf(o3));
    *(float4*)(out + (size_t)n * 256 + 128 + lane * 4) =
        make_float4(roundtf(o4), roundtf(o5), roundtf(o6), roundtf(o7));
    if (out_h) {
        __half2 p01 = __floats2half2_rn(o0, o1), p23 = __floats2half2_rn(o2, o3);
        __half2 p45 = __floats2half2_rn(o4, o5), p67 = __floats2half2_rn(o6, o7);
        uint2 w0, w1;
        w0.x = *(uint32_t*)&p01; w0.y = *(uint32_t*)&p23;
        w1.x = *(uint32_t*)&p45; w1.y = *(uint32_t*)&p67;
        *(uint2*)(out_h + (size_t)n * 256 + lane * 4) = w0;
        *(uint2*)(out_h + (size_t)n * 256 + 128 + lane * 4) = w1;
    }
}

// ---------------- zero per-graph pool ----------------------------------------
__global__ void k_zero_pool() {
    int i = blockIdx.x * blockDim.x + threadIdx.x;
    if (i < N_GRAPHS * 2048) g_pool[i] = 0.f;
}

// ---------------- layer-3: fused softmax+agg+pool (no max pass) --------------
__global__ void k_aggH_pool(const float* __restrict__ h, const __half* __restrict__ hh,
                            const int* __restrict__ batch)
{
    int n0 = blockIdx.x * 32;
    int t = threadIdx.x;   // 256
    __shared__ float a_sm[32][HEADS];
    __shared__ int s_sm[32];
    __shared__ float ad_s[HEADS], avs_s[HEADS], den_s[HEADS];
    int nend = min(n0 + 32, N_NODES);
    if (n0 >= N_NODES) return;
    float pacc[HEADS];
#pragma unroll
    for (int k = 0; k < HEADS; k++) pacc[k] = 0.f;
    int prevb = batch[n0];

    for (int n = n0; n < nend; n++) {
        int bn = batch[n];
        if (bn != prevb) {
#pragma unroll
            for (int k = 0; k < HEADS; k++) {
                atomicAdd(&g_pool[prevb * 2048 + k * 256 + t], pacc[k]);
                pacc[k] = 0.f;
            }
            prevb = bn;
        }
        __syncthreads();
        if (t < 8) {
            float ad = g_ald[n * HEADS + t];
            ad_s[t] = ad;
            float av = __expf(leakyf(g_als[n * HEADS + t] + ad));
            avs_s[t] = av;
            den_s[t] = av;
        }
        __syncthreads();
        int lo = g_rowptr[n], hi = g_rowptr[n + 1];
        float hv = h[(size_t)n * 256 + t];
        float acc[HEADS];
#pragma unroll
        for (int k = 0; k < HEADS; k++)
            acc[k] = avs_s[k] * hv;
        for (int p0 = lo; p0 < hi; p0 += 32) {
            int cnt = min(32, hi - p0);
            __syncthreads();
            if (t < cnt) s_sm[t] = g_csrc[p0 + t];
            __syncthreads();
            if (t < cnt * HEADS) {
                int jj = t >> 3, hd2 = t & 7;
                a_sm[jj][hd2] = __expf(leakyf(g_als[s_sm[jj] * HEADS + hd2] + ad_s[hd2]));
            }
            __syncthreads();
            if (t < 8) {
                float dsum = 0.f;
                for (int jj = 0; jj < cnt; jj++) dsum += a_sm[jj][t];
                den_s[t] += dsum;
            }
            for (int jj = 0; jj < cnt; jj++) {
                float hv2 = __half2float(hh[(size_t)s_sm[jj] * 256 + t]);
#pragma unroll
                for (int k = 0; k < HEADS; k++)
                    acc[k] += a_sm[jj][k] * hv2;
            }
        }
        __syncthreads();
#pragma unroll
        for (int k = 0; k < HEADS; k++)
            pacc[k] += acc[k] / den_s[k];
    }
#pragma unroll
    for (int k = 0; k < HEADS; k++)
        atomicAdd(&g_pool[prevb * 2048 + k * 256 + t], pacc[k]);
}

// ---------------- pool scaling: g_pool[g,:] *= 0.125/cnt(g), tf32-rounded ----
__device__ __forceinline__ int lower_bound_batch(const int* b, int val) {
    int lo = 0, hi = N_NODES;
    while (lo < hi) {
        int mid = (lo + hi) >> 1;
        if (b[mid] < val) lo = mid + 1; else hi = mid;
    }
    return lo;
}
__global__ void k_prep_pool(const int* __restrict__ batch) {
    int g = blockIdx.x;      // 64 blocks x 256 threads
    __shared__ float sc_s;
    if (threadIdx.x == 0) {
        int lo = lower_bound_batch(batch, g);
        int hi = lower_bound_batch(batch, g + 1);
        sc_s = 0.125f / (float)max(hi - lo, 1);
    }
    __syncthreads();
    float sc = sc_s;
#pragma unroll
    for (int i = 0; i < 8; i++) {
        int idx = g * 2048 + i * 256 + threadIdx.x;
        g_pool[idx] = roundtf(g_pool[idx] * sc);
    }
}

// ---------------- classifier MLP ---------------------------------------------
__global__ void k_classifier(const float* __restrict__ Wc1, const float* __restrict__ bc1,
                             const float* __restrict__ Wc2, const float* __restrict__ bc2,
                             float* __restrict__ out)
{
    int g = blockIdx.x;
    int t = threadIdx.x;  // 128
    __shared__ float z[128];
    const float* gr = g_gmean + g * 256;
    float s = bc1[t];
    for (int k = 0; k < 256; k++) s += gr[k] * Wc1[t * 256 + k];
    z[t] = eluf(s);
    __syncthreads();
    if (t < 2) {
        float o = bc2[t];
        for (int jj = 0; jj < 128; jj++) o += z[jj] * Wc2[t * 128 + jj];
        out[g * 2 + t] = o;
    }
}

// ---------------- launch -----------------------------------------------------
extern "C" void kernel_launch(void* const* d_in, const int* in_sizes, int n_in,
                              void* d_out, int out_size)
{
    const float* x      = (const float*)d_in[0];
    const int*   eidx   = (const int*)d_in[1];
    const int*   batch  = (const int*)d_in[2];
    const float* W1  = (const float*)d_in[3];
    const float* as1 = (const float*)d_in[4];
    const float* ad1 = (const float*)d_in[5];
    const float* b1  = (const float*)d_in[6];
    const float* W2  = (const float*)d_in[7];
    const float* as2 = (const float*)d_in[8];
    const float* ad2 = (const float*)d_in[9];
    const float* b2  = (const float*)d_in[10];
    const float* W3  = (const float*)d_in[11];
    const float* as3 = (const float*)d_in[12];
    const float* ad3 = (const float*)d_in[13];
    const float* b3  = (const float*)d_in[14];
    const float* Wc1 = (const float*)d_in[15];
    const float* bc1 = (const float*)d_in[16];
    const float* Wc2 = (const float*)d_in[17];
    const float* bc2 = (const float*)d_in[18];
    float* out = (float*)d_out;

    const int* src = eidx;
    const int* dst = eidx + N_EDGES;

    float*  xp  = nullptr; cudaGetSymbolAddress((void**)&xp,  g_xp);
    __half* xph = nullptr; cudaGetSymbolAddress((void**)&xph, g_xph);
    float*  h   = nullptr; cudaGetSymbolAddress((void**)&h,   g_h);
    __half* hh  = nullptr; cudaGetSymbolAddress((void**)&hh,  g_hh);
    float*  xt  = nullptr; cudaGetSymbolAddress((void**)&xt,  g_xt);
    float*  w1t = nullptr; cudaGetSymbolAddress((void**)&w1t, g_w1t);
    float*  w2t = nullptr; cudaGetSymbolAddress((void**)&w2t, g_w2t);
    float*  Bw  = nullptr; cudaGetSymbolAddress((void**)&Bw,  g_Bw);
    float*  pool = nullptr; cudaGetSymbolAddress((void**)&pool, g_pool);
    float*  gmean = nullptr; cudaGetSymbolAddress((void**)&gmean, g_gmean);
    float*  als = nullptr; cudaGetSymbolAddress((void**)&als, g_als);
    float*  ald = nullptr; cudaGetSymbolAddress((void**)&ald, g_ald);

    cudaFuncSetAttribute(k_mma2, cudaFuncAttributeMaxDynamicSharedMemorySize, GSM_BYTES);

    int gm = (N_NODES + 127) / 128;
    int nwb = (N_NODES + 7) / 8;

    // launch #4 is profiled -> k_scan this round
    k_zero_deg<<<(N_NODES + 255) / 256, 256>>>();                            // 1
    k_hist<<<(N_EDGES + 255) / 256, 256>>>(dst);                             // 2
    k_round<<<(N_NODES * 32 + 255) / 256, 256>>>(x, xt, N_NODES * 32);       // 3
    k_scan<<<1, 1024>>>();                                                   // 4 (profiled)
    k_scatter<<<(N_EDGES + 255) / 256, 256>>>(src, dst);                     // 5
    k_round<<<(256 * 32 + 255) / 256, 256>>>(W1, w1t, 256 * 32);             // 6
    k_round<<<(256 * 256 + 255) / 256, 256>>>(W2, w2t, 256 * 256);           // 7
    k_fold3<<<(2048 + 127) / 128, 128>>>(W3, as3, ad3);                      // 8
    k_zero_pool<<<(N_GRAPHS * 2048 + 255) / 256, 256>>>();                   // 9
    k_permW3<<<(2048 * 256 + 255) / 256, 256>>>(W3);                         // 10

    // ---- layer 1: GEMM (+fused als/ald) then fused softmax+agg
    k_mma2<<<gm, 256, GSM_BYTES>>>(xt, w1t, xp, xph, nullptr,
                                   as1, ad1, als, ald, N_NODES, 32);
    k_gat32<<<nwb, 256>>>(xp, xph, b1, h, nullptr);

    // ---- layer 2
    k_mma2<<<gm, 256, GSM_BYTES>>>(h, w2t, xp, xph, nullptr,
                                   as2, ad2, als, ald, N_NODES, 256);
    k_gat32<<<nwb, 256>>>(xp, xph, b2, h, hh);

    // ---- layer 3: warp-per-node al3, fused softmax+agg+pool, pool GEMM
    k_al3<<<nwb, 256>>>(h);
    k_aggH_pool<<<(N_NODES + 31) / 32, 256>>>(h, hh, batch);
    k_prep_pool<<<N_GRAPHS, 256>>>(batch);
    k_mma2<<<1, 256, GSM_BYTES>>>(pool, Bw, gmean, nullptr, b3,
                                  nullptr, nullptr, nullptr, nullptr, N_GRAPHS, 2048);

    // ---- classifier
    k_classifier<<<N_GRAPHS, 128>>>(Wc1, bc1, Wc2, bc2, out);
}